// round 8
// baseline (speedup 1.0000x reference)
#include <cuda_runtime.h>
#include <math.h>

#define BC 2048   // 32 batch * 64 channels

// ---------------- scratch (device globals: allocation-free) ----------------
__device__ float2 d_X   [BC*128*65];   // rfft2(x)/128^2
__device__ float2 d_T1  [BC*128*65];   // also reused as K0 intermediate A
__device__ float  d_u   [BC*128*128];  // spatial after gelu
__device__ float2 d_P   [BC*64*128];   // forward partial (rows)
__device__ float2 d_U   [BC*64*33];    // kept band spectrum
__device__ float2 d_T2  [BC*128*33];   // inverse rows
__device__ float  d_w   [BC*64*64];    // pooled image
__device__ float2 d_G   [BC*64*33];    // column DFT of pooled
__device__ float2 d_xo  [BC*64*33];    // x_out accumulator

__device__ __forceinline__ void build_tw(float2* tw, int n){
    for (int t = threadIdx.x; t < n; t += blockDim.x){
        float s, c;
        sincospif(2.0f*(float)t/(float)n, &s, &c);
        tw[t] = make_float2(c, s);     // e^{+2*pi*i*t/n}
    }
}

// ---------------- K0a: row-axis forward DFT of input ----------------
// A[img][i][k2] = sum_n2 x[i][n2] * e^{-2pi i k2 n2/128}
__global__ void k0a_kernel(const float* __restrict__ x){
    __shared__ float2 tw[128];
    __shared__ float  row[128];
    int img = blockIdx.y, i = blockIdx.x;
    build_tw(tw, 128);
    const float* xi = x + (size_t)img*128*128 + (size_t)i*128;
    for (int n = threadIdx.x; n < 128; n += blockDim.x) row[n] = xi[n];
    __syncthreads();
    int k2 = threadIdx.x;
    if (k2 >= 65) return;
    float2 A = make_float2(0.f, 0.f);
    int t = 0;
    for (int n2 = 0; n2 < 128; n2++){
        float2 w = tw[t];
        A.x = fmaf(row[n2],  w.x, A.x);
        A.y = fmaf(-row[n2], w.y, A.y);
        t += k2; t &= 127;
    }
    d_T1[(size_t)img*128*65 + (size_t)i*65 + k2] = A;
}

// ---------------- K0b: col-axis forward DFT -> X (with 1/128^2) ----------------
__global__ void k0b_kernel(){
    __shared__ float2 tw[128];
    int img = blockIdx.y;
    int k1b = blockIdx.x * 4;
    build_tw(tw, 128);
    __syncthreads();
    int k2 = threadIdx.x;
    if (k2 >= 65) return;
    const float2* Ai = d_T1 + (size_t)img*128*65;
    float2 acc[4]; int t[4];
    #pragma unroll
    for (int a = 0; a < 4; a++){ acc[a] = make_float2(0.f,0.f); t[a] = 0; }
    for (int i = 0; i < 128; i++){
        float2 v = Ai[(size_t)i*65 + k2];
        #pragma unroll
        for (int a = 0; a < 4; a++){
            float2 w = tw[t[a]];
            acc[a].x = fmaf(v.x, w.x, fmaf( v.y, w.y, acc[a].x));  // v*conj(w)
            acc[a].y = fmaf(v.y, w.x, fmaf(-v.x, w.y, acc[a].y));
            t[a] += k1b + a; t[a] &= 127;
        }
    }
    float2* X = d_X + (size_t)img*128*65;
    const float s = 1.f/16384.f;
    #pragma unroll
    for (int a = 0; a < 4; a++)
        X[(size_t)(k1b+a)*65 + k2] = make_float2(acc[a].x*s, acc[a].y*s);
}

// ---------------- zero x_out ----------------
__global__ void kzero_kernel(){
    size_t n = (size_t)BC*64*33;
    for (size_t i = (size_t)blockIdx.x*blockDim.x + threadIdx.x; i < n;
         i += (size_t)gridDim.x*blockDim.x)
        d_xo[i] = make_float2(0.f, 0.f);
}

// ---------------- K1: gather band-r crop + inverse DFT over rows ----------------
// T1[n1][k2] = sum_{j=0}^{r-1} X[src(j)][k2] * e^{+2pi i j n1 / r}
__global__ void k1_kernel(int r){
    __shared__ float2 tw[128];
    int img = blockIdx.y;
    int n1b = blockIdx.x * 4;
    int c = r/2 + 1;
    build_tw(tw, r);
    __syncthreads();
    int k2 = threadIdx.x;
    if (k2 >= c) return;
    const float2* Xi = d_X  + (size_t)img*128*65;
    float2*       T  = d_T1 + (size_t)img*128*65;
    float2 acc[4]; int t[4], st[4];
    #pragma unroll
    for (int a = 0; a < 4; a++){
        acc[a] = make_float2(0.f,0.f); t[a] = 0;
        int n1 = n1b + a; if (n1 >= r) n1 -= r;
        st[a] = n1;
    }
    int half = r/2;
    for (int j = 0; j < r; j++){
        int src = (j < half) ? j : (128 - r + j);
        float2 v = Xi[(size_t)src*65 + k2];
        #pragma unroll
        for (int a = 0; a < 4; a++){
            float2 w = tw[t[a]];
            acc[a].x = fmaf(v.x, w.x, fmaf(-v.y, w.y, acc[a].x));
            acc[a].y = fmaf(v.x, w.y, fmaf( v.y, w.x, acc[a].y));
            t[a] += st[a]; if (t[a] >= r) t[a] -= r;
        }
    }
    #pragma unroll
    for (int a = 0; a < 4; a++){
        int n1 = n1b + a;
        if (n1 < r) T[(size_t)n1*65 + k2] = acc[a];
    }
}

// ---------------- K2: inverse real DFT over cols (forward-norm irfft = raw sum), then gelu ----------------
__global__ void k2_kernel(int r){
    __shared__ float2 tw[128];
    __shared__ float2 rowA[65], rowB[65];
    int img = blockIdx.y;
    int n1a = blockIdx.x*2, n1b = n1a + 1;
    int c = r/2 + 1;
    build_tw(tw, r);
    const float2* T = d_T1 + (size_t)img*128*65;
    for (int k = threadIdx.x; k < c; k += blockDim.x){
        float wk = (k == 0 || k == r/2) ? 1.f : 2.f;
        float2 va = T[(size_t)n1a*65 + k]; rowA[k] = make_float2(wk*va.x, wk*va.y);
        float2 vb = T[(size_t)n1b*65 + k]; rowB[k] = make_float2(wk*vb.x, wk*vb.y);
    }
    __syncthreads();
    int n2 = threadIdx.x;
    if (n2 >= r) return;
    float a0 = 0.f, a1 = 0.f; int t = 0;
    for (int k = 0; k < c; k++){
        float2 w = tw[t];
        a0 = fmaf(rowA[k].x, w.x, fmaf(-rowA[k].y, w.y, a0));
        a1 = fmaf(rowB[k].x, w.x, fmaf(-rowB[k].y, w.y, a1));
        t += n2; if (t >= r) t -= r;
    }
    // norm='forward' inverse transform carries NO scale factor: raw sum is correct.
    a0 = 0.5f*a0*(1.f + erff(a0*0.70710678118654752f));
    a1 = 0.5f*a1*(1.f + erff(a1*0.70710678118654752f));
    float* u = d_u + (size_t)img*128*128;
    u[(size_t)n1a*128 + n2] = a0;
    u[(size_t)n1b*128 + n2] = a1;
}

// ---------------- K3: forward DFT over rows, only kept frequencies ----------------
// P[q][n2] = sum_{n1} u[n1][n2] * e^{-2pi i kq n1 / r},  kq = q<rp ? q : r-m+q
__global__ void k3_kernel(int r, int m, int rp){
    __shared__ float2 tw[128];
    int img = blockIdx.y;
    int q0 = blockIdx.x*2, q1 = q0 + 1;
    build_tw(tw, r);
    __syncthreads();
    int n2 = threadIdx.x;
    if (n2 >= r) return;
    const float* u = d_u + (size_t)img*128*128;
    int kq0 = (q0 < rp) ? q0 : (r - m + q0);
    int kq1 = (q1 < rp) ? q1 : (r - m + q1);
    if (kq1 >= r) kq1 -= r;   // harmless clamp for overhang tile
    float2 A0 = make_float2(0.f,0.f), A1 = make_float2(0.f,0.f);
    int t0 = 0, t1 = 0;
    for (int n1 = 0; n1 < r; n1++){
        float v = u[(size_t)n1*128 + n2];
        float2 w0 = tw[t0];
        A0.x = fmaf(v,  w0.x, A0.x);
        A0.y = fmaf(-v, w0.y, A0.y);
        t0 += kq0; if (t0 >= r) t0 -= r;
        float2 w1 = tw[t1];
        A1.x = fmaf(v,  w1.x, A1.x);
        A1.y = fmaf(-v, w1.y, A1.y);
        t1 += kq1; if (t1 >= r) t1 -= r;
    }
    float2* P = d_P + (size_t)img*64*128;
    P[(size_t)q0*128 + n2] = A0;
    if (q1 < m) P[(size_t)q1*128 + n2] = A1;
}

// ---------------- K4: forward DFT over cols (half spectrum of band), apply 1/r^2 ----------------
// U[q][k2] = (1/r^2) * sum_{n2} P[q][n2] * e^{-2pi i k2 n2 / r}
// The 1/r^2 is the norm='forward' factor of rfft2(xr) inside the second
// ds_keepsize; the subsequent forward-norm irfft2 (K5/K6) carries no factor.
__global__ void k4_kernel(int r, int c2, float invr2){
    __shared__ float2 tw[128];
    __shared__ float2 Prow[128];
    int img = blockIdx.y, q = blockIdx.x;
    build_tw(tw, r);
    const float2* P = d_P + (size_t)img*64*128;
    for (int i = threadIdx.x; i < r; i += blockDim.x) Prow[i] = P[(size_t)q*128 + i];
    __syncthreads();
    int k2 = threadIdx.x;
    if (k2 >= c2) return;
    float2 A = make_float2(0.f,0.f); int t = 0;
    for (int n2 = 0; n2 < r; n2++){
        float2 v = Prow[n2];
        float2 w = tw[t];
        A.x = fmaf(v.x, w.x, fmaf( v.y, w.y, A.x));
        A.y = fmaf(v.y, w.x, fmaf(-v.x, w.y, A.y));
        t += k2; if (t >= r) t -= r;
    }
    d_U[(size_t)img*64*33 + (size_t)q*33 + k2] = make_float2(A.x*invr2, A.y*invr2);
}

// ---------------- K5: inverse DFT over rows from kept frequencies ----------------
// T2[n1][k2] = sum_q U[q][k2] * e^{+2pi i kq n1 / r}
__global__ void k5_kernel(int r, int m, int rp, int c2){
    __shared__ float2 tw[128];
    int img = blockIdx.y;
    int n1b = blockIdx.x*4;
    build_tw(tw, r);
    __syncthreads();
    int k2 = threadIdx.x;
    if (k2 >= c2) return;
    const float2* U = d_U + (size_t)img*64*33;
    float2 acc[4]; int t[4], st[4], jp[4];
    #pragma unroll
    for (int a = 0; a < 4; a++){
        acc[a] = make_float2(0.f,0.f); t[a] = 0;
        int n1 = n1b + a; if (n1 >= r) n1 -= r;
        st[a] = n1;
        jp[a] = (int)(((long long)(r - m + 1) * (long long)n1) % (long long)r);
    }
    for (int q = 0; q < m; q++){
        float2 v = U[(size_t)q*33 + k2];
        bool atJump = (q == rp - 1);
        #pragma unroll
        for (int a = 0; a < 4; a++){
            float2 w = tw[t[a]];
            acc[a].x = fmaf(v.x, w.x, fmaf(-v.y, w.y, acc[a].x));
            acc[a].y = fmaf(v.x, w.y, fmaf( v.y, w.x, acc[a].y));
            int step = atJump ? jp[a] : st[a];
            t[a] += step; if (t[a] >= r) t[a] -= r;
        }
    }
    float2* T2 = d_T2 + (size_t)img*128*33;
    #pragma unroll
    for (int a = 0; a < 4; a++){
        int n1 = n1b + a;
        if (n1 < r) T2[(size_t)n1*33 + k2] = acc[a];
    }
}

// ---------------- K6: inverse real DFT over cols + fused 2x2 maxpool ----------------
__global__ void k6_kernel(int r, int c2){
    __shared__ float2 tw[128];
    __shared__ float2 rowA[33], rowB[33];
    __shared__ float  sv[128];
    int img = blockIdx.y;
    int p = blockIdx.x;
    int n1a = 2*p, n1b = 2*p + 1;
    build_tw(tw, r);
    const float2* T2 = d_T2 + (size_t)img*128*33;
    for (int k = threadIdx.x; k < c2; k += blockDim.x){
        float wk = (k == 0) ? 1.f : 2.f;
        float2 a = T2[(size_t)n1a*33 + k]; rowA[k] = make_float2(wk*a.x, wk*a.y);
        float2 b = T2[(size_t)n1b*33 + k]; rowB[k] = make_float2(wk*b.x, wk*b.y);
    }
    __syncthreads();
    int n2 = threadIdx.x;
    if (n2 < r){
        float v0 = 0.f, v1 = 0.f; int t = 0;
        for (int k = 0; k < c2; k++){
            float2 w = tw[t];
            v0 = fmaf(rowA[k].x, w.x, fmaf(-rowA[k].y, w.y, v0));
            v1 = fmaf(rowB[k].x, w.x, fmaf(-rowB[k].y, w.y, v1));
            t += n2; if (t >= r) t -= r;
        }
        sv[n2] = fmaxf(v0, v1);
    }
    __syncthreads();
    if (n2 < r/2){
        float* w = d_w + (size_t)img*64*64;
        w[(size_t)p*64 + n2] = fmaxf(sv[2*n2], sv[2*n2+1]);
    }
}

// ---------------- K8a: forward DFT over cols of pooled image ----------------
// G[n1][k2] = sum_{n2} w[n1][n2] * e^{-2pi i k2 n2 / cp}, k2 = 0..ncol-1
__global__ void k8a_kernel(int cp, int ncol){
    __shared__ float2 tw[64];
    __shared__ float  wrow[64];
    int img = blockIdx.y, n1 = blockIdx.x;
    build_tw(tw, cp);
    const float* w = d_w + (size_t)img*64*64;
    for (int i = threadIdx.x; i < cp; i += blockDim.x) wrow[i] = w[(size_t)n1*64 + i];
    __syncthreads();
    int k2 = threadIdx.x;
    if (k2 >= ncol) return;
    float2 A = make_float2(0.f,0.f); int t = 0;
    for (int n2 = 0; n2 < cp; n2++){
        float2 ww = tw[t];
        A.x = fmaf(wrow[n2],  ww.x, A.x);
        A.y = fmaf(-wrow[n2], ww.y, A.y);
        t += k2; if (t >= cp) t -= cp;
    }
    d_G[(size_t)img*64*33 + (size_t)n1*33 + k2] = A;
}

// ---------------- K8b: shell entries of xf = rfft2(w)/cp^2, scatter into x_out ----------------
__global__ void k8b_kernel(int cp){
    __shared__ float2 tw[64];
    int img = blockIdx.x;
    build_tw(tw, cp);
    __syncthreads();
    int h = cp/2;
    int codd = cp & 1;
    int nE = (codd ? 2*(h+1) : (h+1)) + cp;
    int e = threadIdx.x;
    if (e >= nE) return;
    int rho, k2, trow;
    if (codd){
        if (e < h+1)            { rho = h;   k2 = e;        trow = h; }
        else if (e < 2*(h+1))   { rho = h+1; k2 = e-(h+1);  trow = 64-h; }
        else { int q = e - 2*(h+1); rho = q; k2 = h; trow = (q <= h) ? q : 64 - (cp - q); }
    } else {
        if (e < h+1)            { rho = h;   k2 = e;        trow = 64-h; }
        else { int q = e - (h+1);   rho = q; k2 = h; trow = (q < h) ? q : 64 - (cp - q); }
    }
    const float2* G = d_G + (size_t)img*64*33;
    float2 A = make_float2(0.f,0.f); int t = 0;
    for (int n1 = 0; n1 < cp; n1++){
        float2 v = G[(size_t)n1*33 + k2];
        float2 w = tw[t];
        A.x = fmaf(v.x, w.x, fmaf( v.y, w.y, A.x));  // v * conj(w)
        A.y = fmaf(v.y, w.x, fmaf(-v.x, w.y, A.y));
        t += rho; if (t >= cp) t -= cp;
    }
    float inv = 1.f/((float)cp*(float)cp);
    d_xo[(size_t)img*64*33 + (size_t)trow*33 + k2] = make_float2(A.x*inv, A.y*inv);
}

// ---------------- K8base: full 8x5 spectrum block for base resolution ----------------
__global__ void k8base_kernel(){
    __shared__ float2 tw[8];
    int img = blockIdx.x;
    build_tw(tw, 8);
    __syncthreads();
    int e = threadIdx.x;
    if (e >= 40) return;
    int q = e/5, k2 = e%5;
    const float2* G = d_G + (size_t)img*64*33;
    float2 A = make_float2(0.f,0.f);
    for (int n1 = 0; n1 < 8; n1++){
        float2 v = G[(size_t)n1*33 + k2];
        float2 w = tw[(q*n1) & 7];
        A.x = fmaf(v.x, w.x, fmaf( v.y, w.y, A.x));
        A.y = fmaf(v.y, w.x, fmaf(-v.x, w.y, A.y));
    }
    int trow = (q < 4) ? q : (56 + q);
    d_xo[(size_t)img*64*33 + (size_t)trow*33 + k2] = make_float2(A.x*(1.f/64.f), A.y*(1.f/64.f));
}

// ---------------- K9: analytic fft2(irfft2(x_out)) symmetrization -> output ----------------
__global__ void k9_kernel(float* __restrict__ out){
    int img = blockIdx.y;
    int k1  = blockIdx.x;
    int k2  = threadIdx.x;   // 0..63
    const float2* xo = d_xo + (size_t)img*64*33;
    int k1n = (64 - k1) & 63;
    float2 v;
    if (k2 >= 1 && k2 <= 31){
        v = xo[(size_t)k1*33 + k2];
    } else if (k2 >= 33){
        float2 a = xo[(size_t)k1n*33 + (64 - k2)];
        v = make_float2(a.x, -a.y);
    } else { // k2 == 0 or 32
        float2 a = xo[(size_t)k1*33 + k2];
        float2 b = xo[(size_t)k1n*33 + k2];
        v = make_float2(0.5f*(a.x + b.x), 0.5f*(a.y - b.y));
    }
    size_t o = (((size_t)img*64 + k1)*64 + k2)*2;
    out[o]   = v.x;
    out[o+1] = v.y;
}

static inline int rup(int n){ return ((n + 31)/32)*32; }

extern "C" void kernel_launch(void* const* d_in, const int* in_sizes, int n_in,
                              void* d_out, int out_size){
    const float* x = (const float*)d_in[0];
    float* out = (float*)d_out;
    (void)in_sizes; (void)n_in; (void)out_size;

    // X = rfft2(x, norm='forward')
    k0a_kernel<<<dim3(128, BC), 128>>>(x);
    k0b_kernel<<<dim3(32,  BC),  96>>>();
    kzero_kernel<<<2048, 256>>>();

    // base_res (16) + increment loop (18..128 step 2), ascending order
    for (int r = 16; r <= 128; r += 2){
        int c   = r/2 + 1;        // rfft cols at size r
        int m   = r/2;            // second low-pass band = ceil(r/2)
        int rp  = (m + 1)/2;      // positive-freq rows kept (incl DC)
        int c2  = m/2 + 1;        // rfft cols of band m
        int cp  = r/2;            // pooled spatial size
        float invr2 = 1.f/((float)r*(float)r);

        k1_kernel<<<dim3((r+3)/4, BC), rup(c)>>>(r);
        k2_kernel<<<dim3(r/2,     BC), rup(r)>>>(r);
        k3_kernel<<<dim3((m+1)/2, BC), rup(r)>>>(r, m, rp);
        k4_kernel<<<dim3(m,       BC), rup(c2)>>>(r, c2, invr2);
        k5_kernel<<<dim3((r+3)/4, BC), rup(c2)>>>(r, m, rp, c2);
        k6_kernel<<<dim3(r/2,     BC), rup(r)>>>(r, c2);
        k8a_kernel<<<dim3(cp,     BC), rup(cp/2 + 1)>>>(cp, cp/2 + 1);
        if (r == 16) k8base_kernel<<<BC, 64>>>();
        else         k8b_kernel<<<BC, 128>>>(cp);
    }

    k9_kernel<<<dim3(64, BC), 64>>>(out);
}

// round 10
// speedup vs baseline: 1.5916x; 1.5916x over previous
#include <cuda_runtime.h>
#include <math.h>

#define BC 2048   // 32 batch * 64 channels

// ---------------- scratch (device globals: allocation-free) ----------------
__device__ float2 d_X   [BC*128*65];
__device__ float2 d_T1  [BC*128*65];
__device__ float  d_u   [BC*128*128];
__device__ float2 d_P   [BC*64*128];
__device__ float2 d_U   [BC*64*33];
__device__ float2 d_T2  [BC*128*33];
__device__ float  d_w   [BC*64*64];
__device__ float2 d_G   [BC*64*33];
__device__ float2 d_xo  [BC*64*33];
// DFT matrices W_n[a*n+b] = e^{+2pi i (a*b mod n)/n} for n = 8..128
__device__ float2 d_W   [707124];

__host__ __device__ __forceinline__ long long offW(int n){
    long long x = n - 1;
    return x*(x+1)*(2*x+1)/6 - 140;   // sum_{m=8}^{n-1} m^2
}

// ---------------- build all DFT matrices ----------------
__global__ void kW_kernel(){
    int n = blockIdx.x + 8;
    float2* W = d_W + offW(n);
    int nn = n*n;
    float inv = 1.0f/(float)n;
    for (int idx = threadIdx.x; idx < nn; idx += blockDim.x){
        int a = idx / n, b = idx - a*n;
        int t = (int)(((long long)a*(long long)b) % (long long)n);
        float s, c;
        sincospif(2.0f*(float)t*inv, &s, &c);
        W[idx] = make_float2(c, s);
    }
}

// ---------------- K0a: row-axis forward DFT of input (4 rows/block) ----------------
__global__ void k0a_kernel(const float* __restrict__ x){
    __shared__ float s0[2][4][128];
    int ty = threadIdx.y, tx = threadIdx.x;
    int img = blockIdx.y*blockDim.y + ty;
    int i0 = blockIdx.x*4;
    const float* xi = x + (size_t)img*128*128 + (size_t)i0*128;
    for (int idx = tx; idx < 4*128; idx += blockDim.x)
        s0[ty][idx>>7][idx&127] = xi[idx];
    __syncthreads();
    int k2 = tx;
    if (k2 >= 65) return;
    const float2* W = d_W + offW(128);
    float2 A0={0.f,0.f},A1={0.f,0.f},A2={0.f,0.f},A3={0.f,0.f};
    for (int n2 = 0; n2 < 128; n2++){
        float2 w = W[n2*128 + k2];
        float v0=s0[ty][0][n2], v1=s0[ty][1][n2], v2=s0[ty][2][n2], v3=s0[ty][3][n2];
        A0.x = fmaf(v0,w.x,A0.x); A0.y = fmaf(-v0,w.y,A0.y);
        A1.x = fmaf(v1,w.x,A1.x); A1.y = fmaf(-v1,w.y,A1.y);
        A2.x = fmaf(v2,w.x,A2.x); A2.y = fmaf(-v2,w.y,A2.y);
        A3.x = fmaf(v3,w.x,A3.x); A3.y = fmaf(-v3,w.y,A3.y);
    }
    float2* T = d_T1 + (size_t)img*128*65;
    T[(size_t)(i0+0)*65+k2]=A0; T[(size_t)(i0+1)*65+k2]=A1;
    T[(size_t)(i0+2)*65+k2]=A2; T[(size_t)(i0+3)*65+k2]=A3;
}

// ---------------- K0b: col-axis forward DFT -> X (with 1/128^2) ----------------
__global__ void k0b_kernel(){
    __shared__ float2 sW[4*128];
    int ty = threadIdx.y, tx = threadIdx.x;
    int tid = ty*blockDim.x + tx, nt = blockDim.x*blockDim.y;
    int k1b = blockIdx.x*4;
    const float2* W = d_W + offW(128);
    for (int idx = tid; idx < 4*128; idx += nt)
        sW[idx] = W[(k1b + (idx>>7))*128 + (idx&127)];
    __syncthreads();
    int img = blockIdx.y*blockDim.y + ty;
    int k2 = tx;
    if (k2 >= 65) return;
    const float2* Ai = d_T1 + (size_t)img*128*65;
    float2 acc[4];
    #pragma unroll
    for (int a = 0; a < 4; a++) acc[a] = make_float2(0.f,0.f);
    for (int i = 0; i < 128; i++){
        float2 v = Ai[(size_t)i*65 + k2];
        #pragma unroll
        for (int a = 0; a < 4; a++){
            float2 w = sW[a*128 + i];
            acc[a].x = fmaf(v.x, w.x, fmaf( v.y, w.y, acc[a].x));  // v*conj(w)
            acc[a].y = fmaf(v.y, w.x, fmaf(-v.x, w.y, acc[a].y));
        }
    }
    float2* X = d_X + (size_t)img*128*65;
    const float s = 1.f/16384.f;
    #pragma unroll
    for (int a = 0; a < 4; a++)
        X[(size_t)(k1b+a)*65 + k2] = make_float2(acc[a].x*s, acc[a].y*s);
}

// ---------------- zero x_out ----------------
__global__ void kzero_kernel(){
    size_t n = (size_t)BC*64*33;
    for (size_t i = (size_t)blockIdx.x*blockDim.x + threadIdx.x; i < n;
         i += (size_t)gridDim.x*blockDim.x)
        d_xo[i] = make_float2(0.f, 0.f);
}

// ---------------- K1: band crop + inverse DFT over rows (4 rows/block) ----------------
__global__ void k1_kernel(int r){
    __shared__ float2 sW[4*128];
    int ty = threadIdx.y, tx = threadIdx.x;
    int tid = ty*blockDim.x + tx, nt = blockDim.x*blockDim.y;
    int n1b = blockIdx.x*4;
    const float2* W = d_W + offW(r);
    for (int idx = tid; idx < 4*r; idx += nt){
        int a = idx / r, j = idx - a*r;
        int n1 = n1b + a;
        if (n1 < r) sW[a*128 + j] = W[n1*r + j];
    }
    __syncthreads();
    int img = blockIdx.y*blockDim.y + ty;
    int c = r/2 + 1, half = r/2;
    int k2 = tx;
    if (k2 >= c) return;
    const float2* Xi = d_X  + (size_t)img*128*65;
    float2*       T  = d_T1 + (size_t)img*128*65;
    float2 acc[4];
    #pragma unroll
    for (int a = 0; a < 4; a++) acc[a] = make_float2(0.f,0.f);
    for (int j = 0; j < r; j++){
        int src = j + ((j >= half) ? (128 - r) : 0);
        float2 v = Xi[(size_t)src*65 + k2];
        #pragma unroll
        for (int a = 0; a < 4; a++){
            float2 w = sW[a*128 + j];
            acc[a].x = fmaf(v.x, w.x, fmaf(-v.y, w.y, acc[a].x));
            acc[a].y = fmaf(v.x, w.y, fmaf( v.y, w.x, acc[a].y));
        }
    }
    #pragma unroll
    for (int a = 0; a < 4; a++){
        int n1 = n1b + a;
        if (n1 < r) T[(size_t)n1*65 + k2] = acc[a];
    }
}

// ---------------- K2: inverse real DFT over cols (raw sum) + gelu ----------------
__global__ void k2_kernel(int r){
    __shared__ float2 sA[8][65], sB[8][65];
    int ty = threadIdx.y, tx = threadIdx.x;
    int img = blockIdx.y*blockDim.y + ty;
    int p = blockIdx.x;
    int n1a = 2*p, n1b = n1a + 1;
    int c = r/2 + 1;
    const float2* T = d_T1 + (size_t)img*128*65;
    for (int k = tx; k < c; k += blockDim.x){
        float wk = (k == 0 || k == r/2) ? 1.f : 2.f;
        float2 va = T[(size_t)n1a*65 + k]; sA[ty][k] = make_float2(wk*va.x, wk*va.y);
        float2 vb = T[(size_t)n1b*65 + k]; sB[ty][k] = make_float2(wk*vb.x, wk*vb.y);
    }
    __syncthreads();
    int n2 = tx;
    if (n2 >= r) return;
    const float2* W = d_W + offW(r);
    float a0 = 0.f, a1 = 0.f;
    for (int k = 0; k < c; k++){
        float2 w = W[k*r + n2];
        float2 rA = sA[ty][k], rB = sB[ty][k];
        a0 = fmaf(rA.x, w.x, fmaf(-rA.y, w.y, a0));
        a1 = fmaf(rB.x, w.x, fmaf(-rB.y, w.y, a1));
    }
    a0 = 0.5f*a0*(1.f + erff(a0*0.70710678118654752f));
    a1 = 0.5f*a1*(1.f + erff(a1*0.70710678118654752f));
    float* u = d_u + (size_t)img*128*128;
    u[(size_t)n1a*128 + n2] = a0;
    u[(size_t)n1b*128 + n2] = a1;
}

// ---------------- K3: forward DFT over rows, kept freqs (4 q/block) ----------------
__global__ void k3_kernel(int r, int m, int rp){
    __shared__ float2 sW3[4*128];
    int ty = threadIdx.y, tx = threadIdx.x;
    int tid = ty*blockDim.x + tx, nt = blockDim.x*blockDim.y;
    int q0 = blockIdx.x*4;
    const float2* W = d_W + offW(r);
    for (int idx = tid; idx < 4*r; idx += nt){
        int a = idx / r, n1 = idx - a*r;
        int q = q0 + a;
        if (q < m){
            int kq = (q < rp) ? q : (r - m + q);
            sW3[a*128 + n1] = W[kq*r + n1];
        } else {
            sW3[a*128 + n1] = make_float2(0.f, 0.f);
        }
    }
    __syncthreads();
    int img = blockIdx.y*blockDim.y + ty;
    int n2 = tx;
    if (n2 >= r) return;
    const float* u = d_u + (size_t)img*128*128;
    float2 A[4];
    #pragma unroll
    for (int a = 0; a < 4; a++) A[a] = make_float2(0.f,0.f);
    for (int n1 = 0; n1 < r; n1++){
        float v = u[(size_t)n1*128 + n2];
        #pragma unroll
        for (int a = 0; a < 4; a++){
            float2 w = sW3[a*128 + n1];
            A[a].x = fmaf(v,  w.x, A[a].x);
            A[a].y = fmaf(-v, w.y, A[a].y);
        }
    }
    float2* P = d_P + (size_t)img*64*128;
    #pragma unroll
    for (int a = 0; a < 4; a++){
        int q = q0 + a;
        if (q < m) P[(size_t)q*128 + n2] = A[a];
    }
}

// ---------------- K4: forward DFT over cols (half spectrum), apply 1/r^2 ----------------
__global__ void k4_kernel(int r, int c2, float invr2, int m){
    __shared__ float2 sP[8][2][128];
    int ty = threadIdx.y, tx = threadIdx.x;
    int img = blockIdx.y*blockDim.y + ty;
    int q0 = blockIdx.x*2, q1 = q0 + 1;
    const float2* P = d_P + (size_t)img*64*128;
    for (int i = tx; i < r; i += blockDim.x){
        sP[ty][0][i] = P[(size_t)q0*128 + i];
        sP[ty][1][i] = (q1 < m) ? P[(size_t)q1*128 + i] : make_float2(0.f,0.f);
    }
    __syncthreads();
    int k2 = tx;
    if (k2 >= c2) return;
    const float2* W = d_W + offW(r);
    float2 A0 = make_float2(0.f,0.f), A1 = make_float2(0.f,0.f);
    for (int n2 = 0; n2 < r; n2++){
        float2 w = W[n2*r + k2];
        float2 v0 = sP[ty][0][n2], v1 = sP[ty][1][n2];
        A0.x = fmaf(v0.x, w.x, fmaf( v0.y, w.y, A0.x));
        A0.y = fmaf(v0.y, w.x, fmaf(-v0.x, w.y, A0.y));
        A1.x = fmaf(v1.x, w.x, fmaf( v1.y, w.y, A1.x));
        A1.y = fmaf(v1.y, w.x, fmaf(-v1.x, w.y, A1.y));
    }
    float2* U = d_U + (size_t)img*64*33;
    U[(size_t)q0*33 + k2] = make_float2(A0.x*invr2, A0.y*invr2);
    if (q1 < m) U[(size_t)q1*33 + k2] = make_float2(A1.x*invr2, A1.y*invr2);
}

// ---------------- K5: inverse DFT over rows from kept freqs (4 rows/block) ----------------
__global__ void k5_kernel(int r, int m, int rp, int c2){
    __shared__ float2 sW5[4*64];
    int ty = threadIdx.y, tx = threadIdx.x;
    int tid = ty*blockDim.x + tx, nt = blockDim.x*blockDim.y;
    int n1b = blockIdx.x*4;
    const float2* W = d_W + offW(r);
    for (int idx = tid; idx < 4*m; idx += nt){
        int a = idx / m, q = idx - a*m;
        int n1 = n1b + a;
        if (n1 < r){
            int kq = (q < rp) ? q : (r - m + q);
            sW5[a*64 + q] = W[n1*r + kq];
        }
    }
    __syncthreads();
    int img = blockIdx.y*blockDim.y + ty;
    int k2 = tx;
    if (k2 >= c2) return;
    const float2* U = d_U + (size_t)img*64*33;
    float2 acc[4];
    #pragma unroll
    for (int a = 0; a < 4; a++) acc[a] = make_float2(0.f,0.f);
    for (int q = 0; q < m; q++){
        float2 v = U[(size_t)q*33 + k2];
        #pragma unroll
        for (int a = 0; a < 4; a++){
            float2 w = sW5[a*64 + q];
            acc[a].x = fmaf(v.x, w.x, fmaf(-v.y, w.y, acc[a].x));
            acc[a].y = fmaf(v.x, w.y, fmaf( v.y, w.x, acc[a].y));
        }
    }
    float2* T2 = d_T2 + (size_t)img*128*33;
    #pragma unroll
    for (int a = 0; a < 4; a++){
        int n1 = n1b + a;
        if (n1 < r) T2[(size_t)n1*33 + k2] = acc[a];
    }
}

// ---------------- K6: inverse real DFT over cols + fused 2x2 maxpool ----------------
__global__ void k6_kernel(int r, int c2){
    __shared__ float2 sA[8][33], sB[8][33];
    __shared__ float  sv[8][128];
    int ty = threadIdx.y, tx = threadIdx.x;
    int img = blockIdx.y*blockDim.y + ty;
    int p = blockIdx.x;
    int n1a = 2*p, n1b = 2*p + 1;
    const float2* T2 = d_T2 + (size_t)img*128*33;
    for (int k = tx; k < c2; k += blockDim.x){
        float wk = (k == 0) ? 1.f : 2.f;
        float2 a = T2[(size_t)n1a*33 + k]; sA[ty][k] = make_float2(wk*a.x, wk*a.y);
        float2 b = T2[(size_t)n1b*33 + k]; sB[ty][k] = make_float2(wk*b.x, wk*b.y);
    }
    __syncthreads();
    int n2 = tx;
    if (n2 < r){
        const float2* W = d_W + offW(r);
        float v0 = 0.f, v1 = 0.f;
        for (int k = 0; k < c2; k++){
            float2 w = W[k*r + n2];
            float2 rA = sA[ty][k], rB = sB[ty][k];
            v0 = fmaf(rA.x, w.x, fmaf(-rA.y, w.y, v0));
            v1 = fmaf(rB.x, w.x, fmaf(-rB.y, w.y, v1));
        }
        sv[ty][n2] = fmaxf(v0, v1);
    }
    __syncthreads();
    if (n2 < r/2){
        float* w = d_w + (size_t)img*64*64;
        w[(size_t)p*64 + n2] = fmaxf(sv[ty][2*n2], sv[ty][2*n2+1]);
    }
}

// ---------------- K8a: forward DFT over cols of pooled image (4 rows/block) ----------------
__global__ void k8a_kernel(int cp, int ncol){
    __shared__ float srow[8][4][64];
    int ty = threadIdx.y, tx = threadIdx.x;
    int img = blockIdx.y*blockDim.y + ty;
    int n1b = blockIdx.x*4;
    const float* wi = d_w + (size_t)img*64*64;
    for (int idx = tx; idx < 4*64; idx += blockDim.x){
        int a = idx >> 6, j = idx & 63;
        int n1 = n1b + a;
        srow[ty][a][j] = (n1 < cp && j < cp) ? wi[(size_t)n1*64 + j] : 0.f;
    }
    __syncthreads();
    int k2 = tx;
    if (k2 >= ncol) return;
    const float2* W = d_W + offW(cp);
    float2 A[4];
    #pragma unroll
    for (int a = 0; a < 4; a++) A[a] = make_float2(0.f,0.f);
    for (int n2 = 0; n2 < cp; n2++){
        float2 w = W[n2*cp + k2];
        #pragma unroll
        for (int a = 0; a < 4; a++){
            float v = srow[ty][a][n2];
            A[a].x = fmaf(v,  w.x, A[a].x);
            A[a].y = fmaf(-v, w.y, A[a].y);
        }
    }
    float2* G = d_G + (size_t)img*64*33;
    #pragma unroll
    for (int a = 0; a < 4; a++){
        int n1 = n1b + a;
        if (n1 < cp) G[(size_t)n1*33 + k2] = A[a];
    }
}

// ---------------- K8b: shell entries of xf = rfft2(w)/cp^2, scatter into x_out ----------------
__global__ void k8b_kernel(int cp){
    __shared__ float2 tw[64];
    int img = blockIdx.x;
    {
        const float2* W = d_W + offW(cp);
        for (int t = threadIdx.x; t < cp; t += blockDim.x) tw[t] = W[cp + t]; // row 1 = period table
    }
    __syncthreads();
    int h = cp/2;
    int codd = cp & 1;
    int nE = (codd ? 2*(h+1) : (h+1)) + cp;
    int e = threadIdx.x;
    if (e >= nE) return;
    int rho, k2, trow;
    if (codd){
        if (e < h+1)            { rho = h;   k2 = e;        trow = h; }
        else if (e < 2*(h+1))   { rho = h+1; k2 = e-(h+1);  trow = 64-h; }
        else { int q = e - 2*(h+1); rho = q; k2 = h; trow = (q <= h) ? q : 64 - (cp - q); }
    } else {
        if (e < h+1)            { rho = h;   k2 = e;        trow = 64-h; }
        else { int q = e - (h+1);   rho = q; k2 = h; trow = (q < h) ? q : 64 - (cp - q); }
    }
    const float2* G = d_G + (size_t)img*64*33;
    float2 A = make_float2(0.f,0.f); int t = 0;
    for (int n1 = 0; n1 < cp; n1++){
        float2 v = G[(size_t)n1*33 + k2];
        float2 w = tw[t];
        A.x = fmaf(v.x, w.x, fmaf( v.y, w.y, A.x));  // v * conj(w)
        A.y = fmaf(v.y, w.x, fmaf(-v.x, w.y, A.y));
        t += rho; if (t >= cp) t -= cp;
    }
    float inv = 1.f/((float)cp*(float)cp);
    d_xo[(size_t)img*64*33 + (size_t)trow*33 + k2] = make_float2(A.x*inv, A.y*inv);
}

// ---------------- K8base: full 8x5 spectrum block for base resolution ----------------
__global__ void k8base_kernel(){
    int img = blockIdx.x;
    int e = threadIdx.x;
    if (e >= 40) return;
    int q = e/5, k2 = e%5;
    const float2* W8 = d_W;  // offW(8) == 0
    const float2* G = d_G + (size_t)img*64*33;
    float2 A = make_float2(0.f,0.f);
    for (int n1 = 0; n1 < 8; n1++){
        float2 v = G[(size_t)n1*33 + k2];
        float2 w = W8[q*8 + n1];
        A.x = fmaf(v.x, w.x, fmaf( v.y, w.y, A.x));
        A.y = fmaf(v.y, w.x, fmaf(-v.x, w.y, A.y));
    }
    int trow = (q < 4) ? q : (56 + q);
    d_xo[(size_t)img*64*33 + (size_t)trow*33 + k2] = make_float2(A.x*(1.f/64.f), A.y*(1.f/64.f));
}

// ---------------- K9: analytic fft2(irfft2(x_out)) symmetrization -> output ----------------
__global__ void k9_kernel(float* __restrict__ out){
    int img = blockIdx.y;
    int k1  = blockIdx.x;
    int k2  = threadIdx.x;   // 0..63
    const float2* xo = d_xo + (size_t)img*64*33;
    int k1n = (64 - k1) & 63;
    float2 v;
    if (k2 >= 1 && k2 <= 31){
        v = xo[(size_t)k1*33 + k2];
    } else if (k2 >= 33){
        float2 a = xo[(size_t)k1n*33 + (64 - k2)];
        v = make_float2(a.x, -a.y);
    } else {
        float2 a = xo[(size_t)k1*33 + k2];
        float2 b = xo[(size_t)k1n*33 + k2];
        v = make_float2(0.5f*(a.x + b.x), 0.5f*(a.y - b.y));
    }
    size_t o = (((size_t)img*64 + k1)*64 + k2)*2;
    out[o]   = v.x;
    out[o+1] = v.y;
}

static inline int rup32(int n){ return ((n + 31)/32)*32; }
static inline int imbFor(int tx){
    int i = 256 / tx;
    if (i > 8) i = 8;
    if (i < 1) i = 1;
    while (i & (i-1)) i--;      // round down to power of 2
    return i;
}

extern "C" void kernel_launch(void* const* d_in, const int* in_sizes, int n_in,
                              void* d_out, int out_size){
    const float* x = (const float*)d_in[0];
    float* out = (float*)d_out;
    (void)in_sizes; (void)n_in; (void)out_size;

    kW_kernel<<<121, 256>>>();

    k0a_kernel<<<dim3(32, BC/2), dim3(96, 2)>>>(x);
    k0b_kernel<<<dim3(32, BC/2), dim3(96, 2)>>>();
    kzero_kernel<<<2048, 256>>>();

    for (int r = 16; r <= 128; r += 2){
        int c    = r/2 + 1;
        int m    = r/2;
        int rp   = (m + 1)/2;
        int c2   = m/2 + 1;
        int cp   = r/2;
        int ncol = cp/2 + 1;
        float invr2 = 1.f/((float)r*(float)r);

        int TX1 = rup32(c),    I1 = imbFor(TX1);
        int TX2 = rup32(r),    I2 = imbFor(TX2);
        int TX4 = rup32(c2),   I4 = imbFor(TX4);
        int TX8 = rup32(ncol), I8 = imbFor(TX8);

        k1_kernel <<<dim3((r+3)/4, BC/I1), dim3(TX1, I1)>>>(r);
        k2_kernel <<<dim3(r/2,     BC/I2), dim3(TX2, I2)>>>(r);
        k3_kernel <<<dim3((m+3)/4, BC/I2), dim3(TX2, I2)>>>(r, m, rp);
        k4_kernel <<<dim3((m+1)/2, BC/I4), dim3(TX4, I4)>>>(r, c2, invr2, m);
        k5_kernel <<<dim3((r+3)/4, BC/I4), dim3(TX4, I4)>>>(r, m, rp, c2);
        k6_kernel <<<dim3(r/2,     BC/I2), dim3(TX2, I2)>>>(r, c2);
        k8a_kernel<<<dim3((cp+3)/4, BC/I8), dim3(TX8, I8)>>>(cp, ncol);
        if (r == 16) k8base_kernel<<<BC, 64>>>();
        else         k8b_kernel<<<BC, 128>>>(cp);
    }

    k9_kernel<<<dim3(64, BC), 64>>>(out);
}

// round 11
// speedup vs baseline: 2.0016x; 1.2576x over previous
#include <cuda_runtime.h>
#include <math.h>

#define BC 2048   // 32 batch * 64 channels

// ---------------- scratch (device globals: allocation-free) ----------------
__device__ float2 d_X   [BC*128*65];
__device__ float2 d_T1  [BC*128*65];
__device__ float  d_u   [BC*128*128];
__device__ float2 d_P   [BC*64*128];
__device__ float2 d_U   [BC*64*33];
__device__ float2 d_T2  [BC*128*33];
__device__ float  d_w   [BC*64*64];
__device__ float2 d_G   [BC*64*33];
__device__ float2 d_xo  [BC*64*33];
// DFT matrices W_n[a*n+b] = e^{+2pi i (a*b mod n)/n} for n = 8..128
__device__ float2 d_W   [707124];

__host__ __device__ __forceinline__ long long offW(int n){
    long long x = n - 1;
    return x*(x+1)*(2*x+1)/6 - 140;   // sum_{m=8}^{n-1} m^2
}

// ---------------- build all DFT matrices ----------------
__global__ void kW_kernel(){
    int n = blockIdx.x + 8;
    float2* W = d_W + offW(n);
    int nn = n*n;
    float inv = 1.0f/(float)n;
    for (int idx = threadIdx.x; idx < nn; idx += blockDim.x){
        int a = idx / n, b = idx - a*n;
        int t = (int)(((long long)a*(long long)b) % (long long)n);
        float s, c;
        sincospif(2.0f*(float)t*inv, &s, &c);
        W[idx] = make_float2(c, s);
    }
}

// ---------------- K0a: row-axis forward DFT of input (4 rows/block) ----------------
__global__ void k0a_kernel(const float* __restrict__ x){
    __shared__ float s0[2][4][128];
    int ty = threadIdx.y, tx = threadIdx.x;
    int img = blockIdx.y*blockDim.y + ty;
    int i0 = blockIdx.x*4;
    const float* xi = x + (size_t)img*128*128 + (size_t)i0*128;
    for (int idx = tx; idx < 4*128; idx += blockDim.x)
        s0[ty][idx>>7][idx&127] = xi[idx];
    __syncthreads();
    int k2 = tx;
    if (k2 >= 65) return;
    const float2* W = d_W + offW(128);
    float2 A0={0.f,0.f},A1={0.f,0.f},A2={0.f,0.f},A3={0.f,0.f};
    for (int n2 = 0; n2 < 128; n2++){
        float2 w = W[n2*128 + k2];
        float v0=s0[ty][0][n2], v1=s0[ty][1][n2], v2=s0[ty][2][n2], v3=s0[ty][3][n2];
        A0.x = fmaf(v0,w.x,A0.x); A0.y = fmaf(-v0,w.y,A0.y);
        A1.x = fmaf(v1,w.x,A1.x); A1.y = fmaf(-v1,w.y,A1.y);
        A2.x = fmaf(v2,w.x,A2.x); A2.y = fmaf(-v2,w.y,A2.y);
        A3.x = fmaf(v3,w.x,A3.x); A3.y = fmaf(-v3,w.y,A3.y);
    }
    float2* T = d_T1 + (size_t)img*128*65;
    T[(size_t)(i0+0)*65+k2]=A0; T[(size_t)(i0+1)*65+k2]=A1;
    T[(size_t)(i0+2)*65+k2]=A2; T[(size_t)(i0+3)*65+k2]=A3;
}

// ---------------- K0b: col-axis forward DFT -> X (with 1/128^2) ----------------
__global__ void k0b_kernel(){
    __shared__ float2 sW[4*128];
    int ty = threadIdx.y, tx = threadIdx.x;
    int tid = ty*blockDim.x + tx, nt = blockDim.x*blockDim.y;
    int k1b = blockIdx.x*4;
    const float2* W = d_W + offW(128);
    for (int idx = tid; idx < 4*128; idx += nt)
        sW[idx] = W[(k1b + (idx>>7))*128 + (idx&127)];
    __syncthreads();
    int img = blockIdx.y*blockDim.y + ty;
    int k2 = tx;
    if (k2 >= 65) return;
    const float2* Ai = d_T1 + (size_t)img*128*65;
    float2 acc[4];
    #pragma unroll
    for (int a = 0; a < 4; a++) acc[a] = make_float2(0.f,0.f);
    for (int i = 0; i < 128; i++){
        float2 v = Ai[(size_t)i*65 + k2];
        #pragma unroll
        for (int a = 0; a < 4; a++){
            float2 w = sW[a*128 + i];
            acc[a].x = fmaf(v.x, w.x, fmaf( v.y, w.y, acc[a].x));  // v*conj(w)
            acc[a].y = fmaf(v.y, w.x, fmaf(-v.x, w.y, acc[a].y));
        }
    }
    float2* X = d_X + (size_t)img*128*65;
    const float s = 1.f/16384.f;
    #pragma unroll
    for (int a = 0; a < 4; a++)
        X[(size_t)(k1b+a)*65 + k2] = make_float2(acc[a].x*s, acc[a].y*s);
}

// ---------------- zero x_out ----------------
__global__ void kzero_kernel(){
    size_t n = (size_t)BC*64*33;
    for (size_t i = (size_t)blockIdx.x*blockDim.x + threadIdx.x; i < n;
         i += (size_t)gridDim.x*blockDim.x)
        d_xo[i] = make_float2(0.f, 0.f);
}

// ---------------- K1: band crop + inverse row DFT, radix-2 DIT ----------------
// Pairs (n1, n1+m), m=r/2: T[n1] = E + t*O, T[n1+m] = E - t*O, t = W_r^{n1}
// E = sum_{j'} Xc[2j']  * W_m^{j' n1};  O = sum_{j'} Xc[2j'+1] * W_m^{j' n1}
__global__ void k1_kernel(int r){
    __shared__ float2 sWh[2][64];
    int ty = threadIdx.y, tx = threadIdx.x;
    int tid = ty*blockDim.x + tx, nt = blockDim.x*blockDim.y;
    int m = r/2;
    int p0 = blockIdx.x*2;
    const float2* Wh = d_W + offW(m);
    for (int idx = tid; idx < 2*m; idx += nt){
        int a = idx / m, j = idx - a*m;
        int n1 = p0 + a;
        sWh[a][j] = (n1 < m) ? Wh[n1*m + j] : make_float2(0.f,0.f);
    }
    __syncthreads();
    int img = blockIdx.y*blockDim.y + ty;
    int c = m + 1, half = m;
    int k2 = tx;
    if (k2 >= c) return;
    const float2* Xi = d_X  + (size_t)img*128*65;
    float2*       T  = d_T1 + (size_t)img*128*65;
    float2 E0={0.f,0.f},O0={0.f,0.f},E1={0.f,0.f},O1={0.f,0.f};
    #pragma unroll 2
    for (int j = 0; j < m; j++){
        int je = 2*j, jo = 2*j + 1;
        int srcE = je + ((je >= half) ? (128 - r) : 0);
        int srcO = jo + ((jo >= half) ? (128 - r) : 0);
        float2 ve = Xi[(size_t)srcE*65 + k2];
        float2 vo = Xi[(size_t)srcO*65 + k2];
        float2 w0 = sWh[0][j], w1 = sWh[1][j];
        E0.x = fmaf(ve.x, w0.x, fmaf(-ve.y, w0.y, E0.x));
        E0.y = fmaf(ve.x, w0.y, fmaf( ve.y, w0.x, E0.y));
        O0.x = fmaf(vo.x, w0.x, fmaf(-vo.y, w0.y, O0.x));
        O0.y = fmaf(vo.x, w0.y, fmaf( vo.y, w0.x, O0.y));
        E1.x = fmaf(ve.x, w1.x, fmaf(-ve.y, w1.y, E1.x));
        E1.y = fmaf(ve.x, w1.y, fmaf( ve.y, w1.x, E1.y));
        O1.x = fmaf(vo.x, w1.x, fmaf(-vo.y, w1.y, O1.x));
        O1.y = fmaf(vo.x, w1.y, fmaf( vo.y, w1.x, O1.y));
    }
    const float2* Wr = d_W + offW(r) + r;   // row 1 of W_r
    #pragma unroll
    for (int a = 0; a < 2; a++){
        int n1 = p0 + a;
        if (n1 >= m) break;
        float2 E = a ? E1 : E0;
        float2 O = a ? O1 : O0;
        float2 t = Wr[n1];                  // e^{+2pi i n1 / r}
        float2 p; p.x = t.x*O.x - t.y*O.y; p.y = t.x*O.y + t.y*O.x;
        T[(size_t)n1*65 + k2]      = make_float2(E.x + p.x, E.y + p.y);
        T[(size_t)(n1+m)*65 + k2]  = make_float2(E.x - p.x, E.y - p.y);
    }
}

// ---------------- K2: inverse real DFT over cols (raw sum) + gelu ----------------
__global__ void k2_kernel(int r){
    __shared__ float2 sA[8][65], sB[8][65];
    int ty = threadIdx.y, tx = threadIdx.x;
    int img = blockIdx.y*blockDim.y + ty;
    int p = blockIdx.x;
    int n1a = 2*p, n1b = n1a + 1;
    int c = r/2 + 1;
    const float2* T = d_T1 + (size_t)img*128*65;
    for (int k = tx; k < c; k += blockDim.x){
        float wk = (k == 0 || k == r/2) ? 1.f : 2.f;
        float2 va = T[(size_t)n1a*65 + k]; sA[ty][k] = make_float2(wk*va.x, wk*va.y);
        float2 vb = T[(size_t)n1b*65 + k]; sB[ty][k] = make_float2(wk*vb.x, wk*vb.y);
    }
    __syncthreads();
    int n2 = tx;
    if (n2 >= r) return;
    const float2* W = d_W + offW(r);
    float a0 = 0.f, a1 = 0.f;
    for (int k = 0; k < c; k++){
        float2 w = W[k*r + n2];
        float2 rA = sA[ty][k], rB = sB[ty][k];
        a0 = fmaf(rA.x, w.x, fmaf(-rA.y, w.y, a0));
        a1 = fmaf(rB.x, w.x, fmaf(-rB.y, w.y, a1));
    }
    a0 = 0.5f*a0*(1.f + erff(a0*0.70710678118654752f));
    a1 = 0.5f*a1*(1.f + erff(a1*0.70710678118654752f));
    float* u = d_u + (size_t)img*128*128;
    u[(size_t)n1a*128 + n2] = a0;
    u[(size_t)n1b*128 + n2] = a1;
}

// ---------------- K3: forward row DFT at kept freqs, fold + Hermitian ----------------
// kq mod m == q, so A[kq] = E'[q] + conj(W_r^{kq}) O'[q] with E',O' length-m
// real-input DFTs (conj exponent). Hermitian: E'[m-q]=conj(E'[q]) -> q <= m/2 only.
__global__ void k3_kernel(int r, int m, int rp){
    __shared__ float2 sW3[2][64];
    int ty = threadIdx.y, tx = threadIdx.x;
    int tid = ty*blockDim.x + tx, nt = blockDim.x*blockDim.y;
    int nq = m/2 + 1;                 // q = 0..m/2 (m even) or 0..(m-1)/2 (m odd)
    int q0 = blockIdx.x*2;
    const float2* Wh = d_W + offW(m);
    for (int idx = tid; idx < 2*m; idx += nt){
        int a = idx / m, j = idx - a*m;
        int q = q0 + a;
        sW3[a][j] = (q < nq) ? Wh[q*m + j] : make_float2(0.f,0.f);
    }
    __syncthreads();
    int img = blockIdx.y*blockDim.y + ty;
    int n2 = tx;
    if (n2 >= r) return;
    const float* u = d_u + (size_t)img*128*128;
    float2 E0={0.f,0.f},O0={0.f,0.f},E1={0.f,0.f},O1={0.f,0.f};
    #pragma unroll 2
    for (int j = 0; j < m; j++){
        float ue = u[(size_t)(2*j)*128 + n2];
        float uo = u[(size_t)(2*j+1)*128 + n2];
        float2 w0 = sW3[0][j], w1 = sW3[1][j];
        E0.x = fmaf(ue,  w0.x, E0.x); E0.y = fmaf(-ue, w0.y, E0.y);
        O0.x = fmaf(uo,  w0.x, O0.x); O0.y = fmaf(-uo, w0.y, O0.y);
        E1.x = fmaf(ue,  w1.x, E1.x); E1.y = fmaf(-ue, w1.y, E1.y);
        O1.x = fmaf(uo,  w1.x, O1.x); O1.y = fmaf(-uo, w1.y, O1.y);
    }
    float2* P = d_P + (size_t)img*64*128;
    const float2* Wr = d_W + offW(r) + r;   // row 1 of W_r
    #pragma unroll
    for (int a = 0; a < 2; a++){
        int q = q0 + a;
        if (q >= nq) break;
        float2 E = a ? E1 : E0;
        float2 O = a ? O1 : O0;
        int kq = (q < rp) ? q : (r - m + q);
        float2 t = Wr[kq];                  // conj -> e^{-2pi i kq/r}
        float tx1 = t.x, ty1 = -t.y;
        float2 A;
        A.x = E.x + tx1*O.x - ty1*O.y;
        A.y = E.y + tx1*O.y + ty1*O.x;
        P[(size_t)q*128 + n2] = A;
        int qm = m - q;
        if (qm > q && qm < m){
            int kqm = (qm < rp) ? qm : (r - m + qm);
            float2 t2 = Wr[kqm];
            float tx2 = t2.x, ty2 = -t2.y;
            float2 Ec = make_float2(E.x, -E.y);
            float2 Oc = make_float2(O.x, -O.y);
            float2 B;
            B.x = Ec.x + tx2*Oc.x - ty2*Oc.y;
            B.y = Ec.y + tx2*Oc.y + ty2*Oc.x;
            P[(size_t)qm*128 + n2] = B;
        }
    }
}

// ---------------- K4: forward DFT over cols (half spectrum), apply 1/r^2 ----------------
__global__ void k4_kernel(int r, int c2, float invr2, int m){
    __shared__ float2 sP[8][2][128];
    int ty = threadIdx.y, tx = threadIdx.x;
    int img = blockIdx.y*blockDim.y + ty;
    int q0 = blockIdx.x*2, q1 = q0 + 1;
    const float2* P = d_P + (size_t)img*64*128;
    for (int i = tx; i < r; i += blockDim.x){
        sP[ty][0][i] = P[(size_t)q0*128 + i];
        sP[ty][1][i] = (q1 < m) ? P[(size_t)q1*128 + i] : make_float2(0.f,0.f);
    }
    __syncthreads();
    int k2 = tx;
    if (k2 >= c2) return;
    const float2* W = d_W + offW(r);
    float2 A0 = make_float2(0.f,0.f), A1 = make_float2(0.f,0.f);
    for (int n2 = 0; n2 < r; n2++){
        float2 w = W[n2*r + k2];
        float2 v0 = sP[ty][0][n2], v1 = sP[ty][1][n2];
        A0.x = fmaf(v0.x, w.x, fmaf( v0.y, w.y, A0.x));
        A0.y = fmaf(v0.y, w.x, fmaf(-v0.x, w.y, A0.y));
        A1.x = fmaf(v1.x, w.x, fmaf( v1.y, w.y, A1.x));
        A1.y = fmaf(v1.y, w.x, fmaf(-v1.x, w.y, A1.y));
    }
    float2* U = d_U + (size_t)img*64*33;
    U[(size_t)q0*33 + k2] = make_float2(A0.x*invr2, A0.y*invr2);
    if (q1 < m) U[(size_t)q1*33 + k2] = make_float2(A1.x*invr2, A1.y*invr2);
}

// ---------------- K5: inverse DFT over rows from kept freqs (4 rows/block) ----------------
__global__ void k5_kernel(int r, int m, int rp, int c2){
    __shared__ float2 sW5[4*64];
    int ty = threadIdx.y, tx = threadIdx.x;
    int tid = ty*blockDim.x + tx, nt = blockDim.x*blockDim.y;
    int n1b = blockIdx.x*4;
    const float2* W = d_W + offW(r);
    for (int idx = tid; idx < 4*m; idx += nt){
        int a = idx / m, q = idx - a*m;
        int n1 = n1b + a;
        if (n1 < r){
            int kq = (q < rp) ? q : (r - m + q);
            sW5[a*64 + q] = W[n1*r + kq];
        }
    }
    __syncthreads();
    int img = blockIdx.y*blockDim.y + ty;
    int k2 = tx;
    if (k2 >= c2) return;
    const float2* U = d_U + (size_t)img*64*33;
    float2 acc[4];
    #pragma unroll
    for (int a = 0; a < 4; a++) acc[a] = make_float2(0.f,0.f);
    for (int q = 0; q < m; q++){
        float2 v = U[(size_t)q*33 + k2];
        #pragma unroll
        for (int a = 0; a < 4; a++){
            float2 w = sW5[a*64 + q];
            acc[a].x = fmaf(v.x, w.x, fmaf(-v.y, w.y, acc[a].x));
            acc[a].y = fmaf(v.x, w.y, fmaf( v.y, w.x, acc[a].y));
        }
    }
    float2* T2 = d_T2 + (size_t)img*128*33;
    #pragma unroll
    for (int a = 0; a < 4; a++){
        int n1 = n1b + a;
        if (n1 < r) T2[(size_t)n1*33 + k2] = acc[a];
    }
}

// ---------------- K6: inverse real DFT over cols + fused 2x2 maxpool ----------------
__global__ void k6_kernel(int r, int c2){
    __shared__ float2 sA[8][33], sB[8][33];
    __shared__ float  sv[8][128];
    int ty = threadIdx.y, tx = threadIdx.x;
    int img = blockIdx.y*blockDim.y + ty;
    int p = blockIdx.x;
    int n1a = 2*p, n1b = 2*p + 1;
    const float2* T2 = d_T2 + (size_t)img*128*33;
    for (int k = tx; k < c2; k += blockDim.x){
        float wk = (k == 0) ? 1.f : 2.f;
        float2 a = T2[(size_t)n1a*33 + k]; sA[ty][k] = make_float2(wk*a.x, wk*a.y);
        float2 b = T2[(size_t)n1b*33 + k]; sB[ty][k] = make_float2(wk*b.x, wk*b.y);
    }
    __syncthreads();
    int n2 = tx;
    if (n2 < r){
        const float2* W = d_W + offW(r);
        float v0 = 0.f, v1 = 0.f;
        for (int k = 0; k < c2; k++){
            float2 w = W[k*r + n2];
            float2 rA = sA[ty][k], rB = sB[ty][k];
            v0 = fmaf(rA.x, w.x, fmaf(-rA.y, w.y, v0));
            v1 = fmaf(rB.x, w.x, fmaf(-rB.y, w.y, v1));
        }
        sv[ty][n2] = fmaxf(v0, v1);
    }
    __syncthreads();
    if (n2 < r/2){
        float* w = d_w + (size_t)img*64*64;
        w[(size_t)p*64 + n2] = fmaxf(sv[ty][2*n2], sv[ty][2*n2+1]);
    }
}

// ---------------- K8a: forward DFT over cols of pooled image (4 rows/block) ----------------
__global__ void k8a_kernel(int cp, int ncol){
    __shared__ float srow[8][4][64];
    int ty = threadIdx.y, tx = threadIdx.x;
    int img = blockIdx.y*blockDim.y + ty;
    int n1b = blockIdx.x*4;
    const float* wi = d_w + (size_t)img*64*64;
    for (int idx = tx; idx < 4*64; idx += blockDim.x){
        int a = idx >> 6, j = idx & 63;
        int n1 = n1b + a;
        srow[ty][a][j] = (n1 < cp && j < cp) ? wi[(size_t)n1*64 + j] : 0.f;
    }
    __syncthreads();
    int k2 = tx;
    if (k2 >= ncol) return;
    const float2* W = d_W + offW(cp);
    float2 A[4];
    #pragma unroll
    for (int a = 0; a < 4; a++) A[a] = make_float2(0.f,0.f);
    for (int n2 = 0; n2 < cp; n2++){
        float2 w = W[n2*cp + k2];
        #pragma unroll
        for (int a = 0; a < 4; a++){
            float v = srow[ty][a][n2];
            A[a].x = fmaf(v,  w.x, A[a].x);
            A[a].y = fmaf(-v, w.y, A[a].y);
        }
    }
    float2* G = d_G + (size_t)img*64*33;
    #pragma unroll
    for (int a = 0; a < 4; a++){
        int n1 = n1b + a;
        if (n1 < cp) G[(size_t)n1*33 + k2] = A[a];
    }
}

// ---------------- K8b: shell entries of xf = rfft2(w)/cp^2, scatter into x_out ----------------
__global__ void k8b_kernel(int cp){
    __shared__ float2 tw[64];
    int img = blockIdx.x;
    {
        const float2* W = d_W + offW(cp);
        for (int t = threadIdx.x; t < cp; t += blockDim.x) tw[t] = W[cp + t];
    }
    __syncthreads();
    int h = cp/2;
    int codd = cp & 1;
    int nE = (codd ? 2*(h+1) : (h+1)) + cp;
    int e = threadIdx.x;
    if (e >= nE) return;
    int rho, k2, trow;
    if (codd){
        if (e < h+1)            { rho = h;   k2 = e;        trow = h; }
        else if (e < 2*(h+1))   { rho = h+1; k2 = e-(h+1);  trow = 64-h; }
        else { int q = e - 2*(h+1); rho = q; k2 = h; trow = (q <= h) ? q : 64 - (cp - q); }
    } else {
        if (e < h+1)            { rho = h;   k2 = e;        trow = 64-h; }
        else { int q = e - (h+1);   rho = q; k2 = h; trow = (q < h) ? q : 64 - (cp - q); }
    }
    const float2* G = d_G + (size_t)img*64*33;
    float2 A = make_float2(0.f,0.f); int t = 0;
    for (int n1 = 0; n1 < cp; n1++){
        float2 v = G[(size_t)n1*33 + k2];
        float2 w = tw[t];
        A.x = fmaf(v.x, w.x, fmaf( v.y, w.y, A.x));  // v * conj(w)
        A.y = fmaf(v.y, w.x, fmaf(-v.x, w.y, A.y));
        t += rho; if (t >= cp) t -= cp;
    }
    float inv = 1.f/((float)cp*(float)cp);
    d_xo[(size_t)img*64*33 + (size_t)trow*33 + k2] = make_float2(A.x*inv, A.y*inv);
}

// ---------------- K8base: full 8x5 spectrum block for base resolution ----------------
__global__ void k8base_kernel(){
    int img = blockIdx.x;
    int e = threadIdx.x;
    if (e >= 40) return;
    int q = e/5, k2 = e%5;
    const float2* W8 = d_W;  // offW(8) == 0
    const float2* G = d_G + (size_t)img*64*33;
    float2 A = make_float2(0.f,0.f);
    for (int n1 = 0; n1 < 8; n1++){
        float2 v = G[(size_t)n1*33 + k2];
        float2 w = W8[q*8 + n1];
        A.x = fmaf(v.x, w.x, fmaf( v.y, w.y, A.x));
        A.y = fmaf(v.y, w.x, fmaf(-v.x, w.y, A.y));
    }
    int trow = (q < 4) ? q : (56 + q);
    d_xo[(size_t)img*64*33 + (size_t)trow*33 + k2] = make_float2(A.x*(1.f/64.f), A.y*(1.f/64.f));
}

// ---------------- K9: analytic fft2(irfft2(x_out)) symmetrization -> output ----------------
__global__ void k9_kernel(float* __restrict__ out){
    int img = blockIdx.y;
    int k1  = blockIdx.x;
    int k2  = threadIdx.x;   // 0..63
    const float2* xo = d_xo + (size_t)img*64*33;
    int k1n = (64 - k1) & 63;
    float2 v;
    if (k2 >= 1 && k2 <= 31){
        v = xo[(size_t)k1*33 + k2];
    } else if (k2 >= 33){
        float2 a = xo[(size_t)k1n*33 + (64 - k2)];
        v = make_float2(a.x, -a.y);
    } else {
        float2 a = xo[(size_t)k1*33 + k2];
        float2 b = xo[(size_t)k1n*33 + k2];
        v = make_float2(0.5f*(a.x + b.x), 0.5f*(a.y - b.y));
    }
    size_t o = (((size_t)img*64 + k1)*64 + k2)*2;
    out[o]   = v.x;
    out[o+1] = v.y;
}

static inline int rup32(int n){ return ((n + 31)/32)*32; }
static inline int imbFor(int tx){
    int i = 256 / tx;
    if (i > 8) i = 8;
    if (i < 1) i = 1;
    while (i & (i-1)) i--;
    return i;
}

extern "C" void kernel_launch(void* const* d_in, const int* in_sizes, int n_in,
                              void* d_out, int out_size){
    const float* x = (const float*)d_in[0];
    float* out = (float*)d_out;
    (void)in_sizes; (void)n_in; (void)out_size;

    kW_kernel<<<121, 256>>>();

    k0a_kernel<<<dim3(32, BC/2), dim3(96, 2)>>>(x);
    k0b_kernel<<<dim3(32, BC/2), dim3(96, 2)>>>();
    kzero_kernel<<<2048, 256>>>();

    for (int r = 16; r <= 128; r += 2){
        int c    = r/2 + 1;
        int m    = r/2;
        int rp   = (m + 1)/2;
        int c2   = m/2 + 1;
        int cp   = r/2;
        int ncol = cp/2 + 1;
        int nq   = m/2 + 1;
        float invr2 = 1.f/((float)r*(float)r);

        int TX1 = rup32(c),    I1 = imbFor(TX1);
        int TX2 = rup32(r),    I2 = imbFor(TX2);
        int TX4 = rup32(c2),   I4 = imbFor(TX4);
        int TX8 = rup32(ncol), I8 = imbFor(TX8);

        k1_kernel <<<dim3((m+1)/2,  BC/I1), dim3(TX1, I1)>>>(r);
        k2_kernel <<<dim3(r/2,      BC/I2), dim3(TX2, I2)>>>(r);
        k3_kernel <<<dim3((nq+1)/2, BC/I2), dim3(TX2, I2)>>>(r, m, rp);
        k4_kernel <<<dim3((m+1)/2,  BC/I4), dim3(TX4, I4)>>>(r, c2, invr2, m);
        k5_kernel <<<dim3((r+3)/4,  BC/I4), dim3(TX4, I4)>>>(r, m, rp, c2);
        k6_kernel <<<dim3(r/2,      BC/I2), dim3(TX2, I2)>>>(r, c2);
        k8a_kernel<<<dim3((cp+3)/4, BC/I8), dim3(TX8, I8)>>>(cp, ncol);
        if (r == 16) k8base_kernel<<<BC, 64>>>();
        else         k8b_kernel<<<BC, 128>>>(cp);
    }

    k9_kernel<<<dim3(64, BC), 64>>>(out);
}

// round 13
// speedup vs baseline: 2.4602x; 1.2292x over previous
#include <cuda_runtime.h>
#include <math.h>

#define BC 2048   // 32 batch * 64 channels

// ---------------- scratch (device globals: allocation-free) ----------------
__device__ float2 d_X   [BC*128*65];
__device__ float2 d_T1  [BC*128*65];
__device__ float  d_u   [BC*128*128];
__device__ float2 d_P   [BC*64*128];
__device__ float2 d_U   [BC*64*33];
__device__ float2 d_T2  [BC*128*33];
__device__ float  d_w   [BC*64*64];
__device__ float2 d_G   [BC*64*33];
__device__ float2 d_xo  [BC*64*33];
// DFT matrices W_n[a*n+b] = e^{+2pi i (a*b mod n)/n} for n = 8..128
__device__ float2 d_W   [707124];

__host__ __device__ __forceinline__ long long offW(int n){
    long long x = n - 1;
    return x*(x+1)*(2*x+1)/6 - 140;   // sum_{m=8}^{n-1} m^2
}

// ---------------- build all DFT matrices ----------------
__global__ void kW_kernel(){
    int n = blockIdx.x + 8;
    float2* W = d_W + offW(n);
    int nn = n*n;
    float inv = 1.0f/(float)n;
    for (int idx = threadIdx.x; idx < nn; idx += blockDim.x){
        int a = idx / n, b = idx - a*n;
        int t = (int)(((long long)a*(long long)b) % (long long)n);
        float s, c;
        sincospif(2.0f*(float)t*inv, &s, &c);
        W[idx] = make_float2(c, s);
    }
}

// ---------------- K0a: row-axis forward DFT of input (4 rows/block) ----------------
__global__ void k0a_kernel(const float* __restrict__ x){
    __shared__ float s0[2][4][128];
    int ty = threadIdx.y, tx = threadIdx.x;
    int img = blockIdx.y*blockDim.y + ty;
    int i0 = blockIdx.x*4;
    const float* xi = x + (size_t)img*128*128 + (size_t)i0*128;
    for (int idx = tx; idx < 4*128; idx += blockDim.x)
        s0[ty][idx>>7][idx&127] = xi[idx];
    __syncthreads();
    int k2 = tx;
    if (k2 >= 65) return;
    const float2* W = d_W + offW(128);
    float2 A0={0.f,0.f},A1={0.f,0.f},A2={0.f,0.f},A3={0.f,0.f};
    for (int n2 = 0; n2 < 128; n2++){
        float2 w = W[n2*128 + k2];
        float v0=s0[ty][0][n2], v1=s0[ty][1][n2], v2=s0[ty][2][n2], v3=s0[ty][3][n2];
        A0.x = fmaf(v0,w.x,A0.x); A0.y = fmaf(-v0,w.y,A0.y);
        A1.x = fmaf(v1,w.x,A1.x); A1.y = fmaf(-v1,w.y,A1.y);
        A2.x = fmaf(v2,w.x,A2.x); A2.y = fmaf(-v2,w.y,A2.y);
        A3.x = fmaf(v3,w.x,A3.x); A3.y = fmaf(-v3,w.y,A3.y);
    }
    float2* T = d_T1 + (size_t)img*128*65;
    T[(size_t)(i0+0)*65+k2]=A0; T[(size_t)(i0+1)*65+k2]=A1;
    T[(size_t)(i0+2)*65+k2]=A2; T[(size_t)(i0+3)*65+k2]=A3;
}

// ---------------- K0b: col-axis forward DFT -> X (with 1/128^2) ----------------
__global__ void k0b_kernel(){
    __shared__ float2 sW[4*128];
    int ty = threadIdx.y, tx = threadIdx.x;
    int tid = ty*blockDim.x + tx, nt = blockDim.x*blockDim.y;
    int k1b = blockIdx.x*4;
    const float2* W = d_W + offW(128);
    for (int idx = tid; idx < 4*128; idx += nt)
        sW[idx] = W[(k1b + (idx>>7))*128 + (idx&127)];
    __syncthreads();
    int img = blockIdx.y*blockDim.y + ty;
    int k2 = tx;
    if (k2 >= 65) return;
    const float2* Ai = d_T1 + (size_t)img*128*65;
    float2 acc[4];
    #pragma unroll
    for (int a = 0; a < 4; a++) acc[a] = make_float2(0.f,0.f);
    for (int i = 0; i < 128; i++){
        float2 v = Ai[(size_t)i*65 + k2];
        #pragma unroll
        for (int a = 0; a < 4; a++){
            float2 w = sW[a*128 + i];
            acc[a].x = fmaf(v.x, w.x, fmaf( v.y, w.y, acc[a].x));  // v*conj(w)
            acc[a].y = fmaf(v.y, w.x, fmaf(-v.x, w.y, acc[a].y));
        }
    }
    float2* X = d_X + (size_t)img*128*65;
    const float s = 1.f/16384.f;
    #pragma unroll
    for (int a = 0; a < 4; a++)
        X[(size_t)(k1b+a)*65 + k2] = make_float2(acc[a].x*s, acc[a].y*s);
}

// ---------------- zero x_out ----------------
__global__ void kzero_kernel(){
    size_t n = (size_t)BC*64*33;
    for (size_t i = (size_t)blockIdx.x*blockDim.x + threadIdx.x; i < n;
         i += (size_t)gridDim.x*blockDim.x)
        d_xo[i] = make_float2(0.f, 0.f);
}

// ---------------- K1: band crop + inverse row DFT, radix-2 DIT ----------------
__global__ void k1_kernel(int r){
    __shared__ float2 sWh[2][64];
    int ty = threadIdx.y, tx = threadIdx.x;
    int tid = ty*blockDim.x + tx, nt = blockDim.x*blockDim.y;
    int m = r/2;
    int p0 = blockIdx.x*2;
    const float2* Wh = d_W + offW(m);
    for (int idx = tid; idx < 2*m; idx += nt){
        int a = idx / m, j = idx - a*m;
        int n1 = p0 + a;
        sWh[a][j] = (n1 < m) ? Wh[n1*m + j] : make_float2(0.f,0.f);
    }
    __syncthreads();
    int img = blockIdx.y*blockDim.y + ty;
    int c = m + 1, half = m;
    int k2 = tx;
    if (k2 >= c) return;
    const float2* Xi = d_X  + (size_t)img*128*65;
    float2*       T  = d_T1 + (size_t)img*128*65;
    float2 E0={0.f,0.f},O0={0.f,0.f},E1={0.f,0.f},O1={0.f,0.f};
    #pragma unroll 2
    for (int j = 0; j < m; j++){
        int je = 2*j, jo = 2*j + 1;
        int srcE = je + ((je >= half) ? (128 - r) : 0);
        int srcO = jo + ((jo >= half) ? (128 - r) : 0);
        float2 ve = Xi[(size_t)srcE*65 + k2];
        float2 vo = Xi[(size_t)srcO*65 + k2];
        float2 w0 = sWh[0][j], w1 = sWh[1][j];
        E0.x = fmaf(ve.x, w0.x, fmaf(-ve.y, w0.y, E0.x));
        E0.y = fmaf(ve.x, w0.y, fmaf( ve.y, w0.x, E0.y));
        O0.x = fmaf(vo.x, w0.x, fmaf(-vo.y, w0.y, O0.x));
        O0.y = fmaf(vo.x, w0.y, fmaf( vo.y, w0.x, O0.y));
        E1.x = fmaf(ve.x, w1.x, fmaf(-ve.y, w1.y, E1.x));
        E1.y = fmaf(ve.x, w1.y, fmaf( ve.y, w1.x, E1.y));
        O1.x = fmaf(vo.x, w1.x, fmaf(-vo.y, w1.y, O1.x));
        O1.y = fmaf(vo.x, w1.y, fmaf( vo.y, w1.x, O1.y));
    }
    const float2* Wr = d_W + offW(r) + r;   // row 1 of W_r
    #pragma unroll
    for (int a = 0; a < 2; a++){
        int n1 = p0 + a;
        if (n1 >= m) break;
        float2 E = a ? E1 : E0;
        float2 O = a ? O1 : O0;
        float2 t = Wr[n1];
        float2 p; p.x = t.x*O.x - t.y*O.y; p.y = t.x*O.y + t.y*O.x;
        T[(size_t)n1*65 + k2]      = make_float2(E.x + p.x, E.y + p.y);
        T[(size_t)(n1+m)*65 + k2]  = make_float2(E.x - p.x, E.y - p.y);
    }
}

// ---------------- K1 radix-4: r % 4 == 0 && r >= 32 ----------------
// One n per block (0..h-1), outputs rows n, n+h, n+m, n+h+m.
__global__ void k1r4_kernel(int r){
    __shared__ float2 sWh[32];
    int ty = threadIdx.y, tx = threadIdx.x;
    int tid = ty*blockDim.x + tx, nt = blockDim.x*blockDim.y;
    int m = r/2, h = r/4;
    int n = blockIdx.x;
    const float2* Wh = d_W + offW(h);
    for (int idx = tid; idx < h; idx += nt) sWh[idx] = Wh[n*h + idx];
    __syncthreads();
    int img = blockIdx.y*blockDim.y + ty;
    int c = m + 1;
    int k2 = tx;
    if (k2 >= c) return;
    const float2* Xi = d_X  + (size_t)img*128*65;
    float2*       T  = d_T1 + (size_t)img*128*65;
    float2 EE={0.f,0.f},EO={0.f,0.f},OE={0.f,0.f},OO={0.f,0.f};
    int sh = 128 - r;
    #pragma unroll 2
    for (int j2 = 0; j2 < h; j2++){
        int j0 = 4*j2, j1 = j0+1, jb = j0+2, j3 = j0+3;
        float2 v0 = Xi[(size_t)(j0 + ((j0>=m)?sh:0))*65 + k2];
        float2 v1 = Xi[(size_t)(j1 + ((j1>=m)?sh:0))*65 + k2];
        float2 v2 = Xi[(size_t)(jb + ((jb>=m)?sh:0))*65 + k2];
        float2 v3 = Xi[(size_t)(j3 + ((j3>=m)?sh:0))*65 + k2];
        float2 w = sWh[j2];
        EE.x = fmaf(v0.x,w.x,fmaf(-v0.y,w.y,EE.x)); EE.y = fmaf(v0.x,w.y,fmaf(v0.y,w.x,EE.y));
        OE.x = fmaf(v1.x,w.x,fmaf(-v1.y,w.y,OE.x)); OE.y = fmaf(v1.x,w.y,fmaf(v1.y,w.x,OE.y));
        EO.x = fmaf(v2.x,w.x,fmaf(-v2.y,w.y,EO.x)); EO.y = fmaf(v2.x,w.y,fmaf(v2.y,w.x,EO.y));
        OO.x = fmaf(v3.x,w.x,fmaf(-v3.y,w.y,OO.x)); OO.y = fmaf(v3.x,w.y,fmaf(v3.y,w.x,OO.y));
    }
    const float2* Wm1 = d_W + offW(m) + m;   // row 1 of W_m
    const float2* Wr1 = d_W + offW(r) + r;   // row 1 of W_r
    float2 tm = Wm1[n];
    float2 tr0 = Wr1[n], tr1 = Wr1[n+h];
    float2 tEO, tOO;
    tEO.x = tm.x*EO.x - tm.y*EO.y; tEO.y = tm.x*EO.y + tm.y*EO.x;
    tOO.x = tm.x*OO.x - tm.y*OO.y; tOO.y = tm.x*OO.y + tm.y*OO.x;
    float2 E0 = make_float2(EE.x+tEO.x, EE.y+tEO.y);
    float2 E1 = make_float2(EE.x-tEO.x, EE.y-tEO.y);
    float2 O0 = make_float2(OE.x+tOO.x, OE.y+tOO.y);
    float2 O1 = make_float2(OE.x-tOO.x, OE.y-tOO.y);
    float2 p0, p1;
    p0.x = tr0.x*O0.x - tr0.y*O0.y; p0.y = tr0.x*O0.y + tr0.y*O0.x;
    p1.x = tr1.x*O1.x - tr1.y*O1.y; p1.y = tr1.x*O1.y + tr1.y*O1.x;
    T[(size_t)n*65 + k2]         = make_float2(E0.x+p0.x, E0.y+p0.y);
    T[(size_t)(n+m)*65 + k2]     = make_float2(E0.x-p0.x, E0.y-p0.y);
    T[(size_t)(n+h)*65 + k2]     = make_float2(E1.x+p1.x, E1.y+p1.y);
    T[(size_t)(n+h+m)*65 + k2]   = make_float2(E1.x-p1.x, E1.y-p1.y);
}

// ---------------- K2: inverse real DFT over cols, radix-2 over k + gelu ----------------
// Thread n2 in 0..m-1 -> outputs n2 and n2+m for both rows.
__global__ void k2_kernel(int r){
    __shared__ float2 sAe[8][33], sAo[8][33], sBe[8][33], sBo[8][33];
    int ty = threadIdx.y, tx = threadIdx.x;
    int img = blockIdx.y*blockDim.y + ty;
    int p = blockIdx.x;
    int n1a = 2*p, n1b = n1a + 1;
    int m = r/2, c = m + 1;
    int mE = m/2 + 1;         // even-k count (k' = 0..floor(m/2))
    int mO = c - mE;          // odd-k count
    const float2* T = d_T1 + (size_t)img*128*65;
    for (int k = tx; k < c; k += blockDim.x){
        float wk = (k == 0 || k == m) ? 1.f : 2.f;
        float2 va = T[(size_t)n1a*65 + k];
        float2 vb = T[(size_t)n1b*65 + k];
        va.x *= wk; va.y *= wk; vb.x *= wk; vb.y *= wk;
        if (k & 1){ sAo[ty][k>>1] = va; sBo[ty][k>>1] = vb; }
        else      { sAe[ty][k>>1] = va; sBe[ty][k>>1] = vb; }
    }
    __syncthreads();
    int n2 = tx;
    if (n2 >= m) return;
    const float2* Wm = d_W + offW(m);
    float eA = 0.f, eB = 0.f;
    float2 oA = {0.f,0.f}, oB = {0.f,0.f};
    for (int k = 0; k < mO; k++){
        float2 w = Wm[k*m + n2];
        float2 ae = sAe[ty][k], be = sBe[ty][k];
        eA = fmaf(ae.x, w.x, fmaf(-ae.y, w.y, eA));
        eB = fmaf(be.x, w.x, fmaf(-be.y, w.y, eB));
        float2 ao = sAo[ty][k], bo = sBo[ty][k];
        oA.x = fmaf(ao.x, w.x, fmaf(-ao.y, w.y, oA.x));
        oA.y = fmaf(ao.x, w.y, fmaf( ao.y, w.x, oA.y));
        oB.x = fmaf(bo.x, w.x, fmaf(-bo.y, w.y, oB.x));
        oB.y = fmaf(bo.x, w.y, fmaf( bo.y, w.x, oB.y));
    }
    if (mE > mO){
        float2 w = Wm[(mE-1)*m + n2];
        float2 ae = sAe[ty][mE-1], be = sBe[ty][mE-1];
        eA = fmaf(ae.x, w.x, fmaf(-ae.y, w.y, eA));
        eB = fmaf(be.x, w.x, fmaf(-be.y, w.y, eB));
    }
    float2 t = d_W[offW(r) + r + n2];      // W_r^{n2}
    float rA = t.x*oA.x - t.y*oA.y;
    float rB = t.x*oB.x - t.y*oB.y;
    float a0 = eA + rA, a2 = eA - rA;
    float b0 = eB + rB, b2 = eB - rB;
    const float K = 0.70710678118654752f;
    a0 = 0.5f*a0*(1.f + erff(a0*K));
    a2 = 0.5f*a2*(1.f + erff(a2*K));
    b0 = 0.5f*b0*(1.f + erff(b0*K));
    b2 = 0.5f*b2*(1.f + erff(b2*K));
    float* u = d_u + (size_t)img*128*128;
    u[(size_t)n1a*128 + n2]     = a0;
    u[(size_t)n1a*128 + n2 + m] = a2;
    u[(size_t)n1b*128 + n2]     = b0;
    u[(size_t)n1b*128 + n2 + m] = b2;
}

// ---------------- K3: forward row DFT at kept freqs, fold + Hermitian ----------------
__global__ void k3_kernel(int r, int m, int rp){
    __shared__ float2 sW3[2][64];
    int ty = threadIdx.y, tx = threadIdx.x;
    int tid = ty*blockDim.x + tx, nt = blockDim.x*blockDim.y;
    int nq = m/2 + 1;
    int q0 = blockIdx.x*2;
    const float2* Wh = d_W + offW(m);
    for (int idx = tid; idx < 2*m; idx += nt){
        int a = idx / m, j = idx - a*m;
        int q = q0 + a;
        sW3[a][j] = (q < nq) ? Wh[q*m + j] : make_float2(0.f,0.f);
    }
    __syncthreads();
    int img = blockIdx.y*blockDim.y + ty;
    int n2 = tx;
    if (n2 >= r) return;
    const float* u = d_u + (size_t)img*128*128;
    float2 E0={0.f,0.f},O0={0.f,0.f},E1={0.f,0.f},O1={0.f,0.f};
    #pragma unroll 2
    for (int j = 0; j < m; j++){
        float ue = u[(size_t)(2*j)*128 + n2];
        float uo = u[(size_t)(2*j+1)*128 + n2];
        float2 w0 = sW3[0][j], w1 = sW3[1][j];
        E0.x = fmaf(ue,  w0.x, E0.x); E0.y = fmaf(-ue, w0.y, E0.y);
        O0.x = fmaf(uo,  w0.x, O0.x); O0.y = fmaf(-uo, w0.y, O0.y);
        E1.x = fmaf(ue,  w1.x, E1.x); E1.y = fmaf(-ue, w1.y, E1.y);
        O1.x = fmaf(uo,  w1.x, O1.x); O1.y = fmaf(-uo, w1.y, O1.y);
    }
    float2* P = d_P + (size_t)img*64*128;
    const float2* Wr = d_W + offW(r) + r;
    #pragma unroll
    for (int a = 0; a < 2; a++){
        int q = q0 + a;
        if (q >= nq) break;
        float2 E = a ? E1 : E0;
        float2 O = a ? O1 : O0;
        int kq = (q < rp) ? q : (r - m + q);
        float2 t = Wr[kq];
        float tx1 = t.x, ty1 = -t.y;
        float2 A;
        A.x = E.x + tx1*O.x - ty1*O.y;
        A.y = E.y + tx1*O.y + ty1*O.x;
        P[(size_t)q*128 + n2] = A;
        int qm = m - q;
        if (qm > q && qm < m){
            int kqm = (qm < rp) ? qm : (r - m + qm);
            float2 t2 = Wr[kqm];
            float tx2 = t2.x, ty2 = -t2.y;
            float2 Ec = make_float2(E.x, -E.y);
            float2 Oc = make_float2(O.x, -O.y);
            float2 B;
            B.x = Ec.x + tx2*Oc.x - ty2*Oc.y;
            B.y = Ec.y + tx2*Oc.y + ty2*Oc.x;
            P[(size_t)qm*128 + n2] = B;
        }
    }
}

// ---------------- K4: forward DFT over cols (half spectrum), apply 1/r^2 ----------------
__global__ void k4_kernel(int r, int c2, float invr2, int m){
    __shared__ float2 sP[8][2][128];
    int ty = threadIdx.y, tx = threadIdx.x;
    int img = blockIdx.y*blockDim.y + ty;
    int q0 = blockIdx.x*2, q1 = q0 + 1;
    const float2* P = d_P + (size_t)img*64*128;
    for (int i = tx; i < r; i += blockDim.x){
        sP[ty][0][i] = P[(size_t)q0*128 + i];
        sP[ty][1][i] = (q1 < m) ? P[(size_t)q1*128 + i] : make_float2(0.f,0.f);
    }
    __syncthreads();
    int k2 = tx;
    if (k2 >= c2) return;
    const float2* W = d_W + offW(r);
    float2 A0 = make_float2(0.f,0.f), A1 = make_float2(0.f,0.f);
    for (int n2 = 0; n2 < r; n2++){
        float2 w = W[n2*r + k2];
        float2 v0 = sP[ty][0][n2], v1 = sP[ty][1][n2];
        A0.x = fmaf(v0.x, w.x, fmaf( v0.y, w.y, A0.x));
        A0.y = fmaf(v0.y, w.x, fmaf(-v0.x, w.y, A0.y));
        A1.x = fmaf(v1.x, w.x, fmaf( v1.y, w.y, A1.x));
        A1.y = fmaf(v1.y, w.x, fmaf(-v1.x, w.y, A1.y));
    }
    float2* U = d_U + (size_t)img*64*33;
    U[(size_t)q0*33 + k2] = make_float2(A0.x*invr2, A0.y*invr2);
    if (q1 < m) U[(size_t)q1*33 + k2] = make_float2(A1.x*invr2, A1.y*invr2);
}

// ---------------- K5: inverse DFT over rows from kept freqs (4 rows/block) ----------------
__global__ void k5_kernel(int r, int m, int rp, int c2){
    __shared__ float2 sW5[4*64];
    int ty = threadIdx.y, tx = threadIdx.x;
    int tid = ty*blockDim.x + tx, nt = blockDim.x*blockDim.y;
    int n1b = blockIdx.x*4;
    const float2* W = d_W + offW(r);
    for (int idx = tid; idx < 4*m; idx += nt){
        int a = idx / m, q = idx - a*m;
        int n1 = n1b + a;
        if (n1 < r){
            int kq = (q < rp) ? q : (r - m + q);
            sW5[a*64 + q] = W[n1*r + kq];
        }
    }
    __syncthreads();
    int img = blockIdx.y*blockDim.y + ty;
    int k2 = tx;
    if (k2 >= c2) return;
    const float2* U = d_U + (size_t)img*64*33;
    float2 acc[4];
    #pragma unroll
    for (int a = 0; a < 4; a++) acc[a] = make_float2(0.f,0.f);
    for (int q = 0; q < m; q++){
        float2 v = U[(size_t)q*33 + k2];
        #pragma unroll
        for (int a = 0; a < 4; a++){
            float2 w = sW5[a*64 + q];
            acc[a].x = fmaf(v.x, w.x, fmaf(-v.y, w.y, acc[a].x));
            acc[a].y = fmaf(v.x, w.y, fmaf( v.y, w.x, acc[a].y));
        }
    }
    float2* T2 = d_T2 + (size_t)img*128*33;
    #pragma unroll
    for (int a = 0; a < 4; a++){
        int n1 = n1b + a;
        if (n1 < r) T2[(size_t)n1*33 + k2] = acc[a];
    }
}

// ---------------- K6: inverse real DFT over cols, radix-2 over k + maxpool ----------------
__global__ void k6_kernel(int r, int c2){
    __shared__ float2 sAe[8][17], sAo[8][17], sBe[8][17], sBo[8][17];
    __shared__ float  sv[8][128];
    int ty = threadIdx.y, tx = threadIdx.x;
    int img = blockIdx.y*blockDim.y + ty;
    int p = blockIdx.x;
    int n1a = 2*p, n1b = 2*p + 1;
    int m = r/2;
    int nE = (c2 + 1)/2, nO = c2/2;
    const float2* T2 = d_T2 + (size_t)img*128*33;
    for (int k = tx; k < c2; k += blockDim.x){
        float wk = (k == 0) ? 1.f : 2.f;
        float2 a = T2[(size_t)n1a*33 + k];
        float2 b = T2[(size_t)n1b*33 + k];
        a.x *= wk; a.y *= wk; b.x *= wk; b.y *= wk;
        if (k & 1){ sAo[ty][k>>1] = a; sBo[ty][k>>1] = b; }
        else      { sAe[ty][k>>1] = a; sBe[ty][k>>1] = b; }
    }
    __syncthreads();
    int n2 = tx;
    if (n2 < m){
        const float2* Wm = d_W + offW(m);
        float eA = 0.f, eB = 0.f;
        float2 oA = {0.f,0.f}, oB = {0.f,0.f};
        for (int k = 0; k < nO; k++){
            float2 w = Wm[k*m + n2];
            float2 ae = sAe[ty][k], be = sBe[ty][k];
            eA = fmaf(ae.x, w.x, fmaf(-ae.y, w.y, eA));
            eB = fmaf(be.x, w.x, fmaf(-be.y, w.y, eB));
            float2 ao = sAo[ty][k], bo = sBo[ty][k];
            oA.x = fmaf(ao.x, w.x, fmaf(-ao.y, w.y, oA.x));
            oA.y = fmaf(ao.x, w.y, fmaf( ao.y, w.x, oA.y));
            oB.x = fmaf(bo.x, w.x, fmaf(-bo.y, w.y, oB.x));
            oB.y = fmaf(bo.x, w.y, fmaf( bo.y, w.x, oB.y));
        }
        if (nE > nO){
            float2 w = Wm[(nE-1)*m + n2];
            float2 ae = sAe[ty][nE-1], be = sBe[ty][nE-1];
            eA = fmaf(ae.x, w.x, fmaf(-ae.y, w.y, eA));
            eB = fmaf(be.x, w.x, fmaf(-be.y, w.y, eB));
        }
        float2 t = d_W[offW(r) + r + n2];
        float rA = t.x*oA.x - t.y*oA.y;
        float rB = t.x*oB.x - t.y*oB.y;
        sv[ty][n2]     = fmaxf(eA + rA, eB + rB);
        sv[ty][n2 + m] = fmaxf(eA - rA, eB - rB);
    }
    __syncthreads();
    if (n2 < m){
        float* w = d_w + (size_t)img*64*64;
        w[(size_t)p*64 + n2] = fmaxf(sv[ty][2*n2], sv[ty][2*n2+1]);
    }
}

// ---------------- K8a: forward DFT over cols of pooled image (4 rows/block) ----------------
__global__ void k8a_kernel(int cp, int ncol){
    __shared__ float srow[8][4][64];
    int ty = threadIdx.y, tx = threadIdx.x;
    int img = blockIdx.y*blockDim.y + ty;
    int n1b = blockIdx.x*4;
    const float* wi = d_w + (size_t)img*64*64;
    for (int idx = tx; idx < 4*64; idx += blockDim.x){
        int a = idx >> 6, j = idx & 63;
        int n1 = n1b + a;
        srow[ty][a][j] = (n1 < cp && j < cp) ? wi[(size_t)n1*64 + j] : 0.f;
    }
    __syncthreads();
    int k2 = tx;
    if (k2 >= ncol) return;
    const float2* W = d_W + offW(cp);
    float2 A[4];
    #pragma unroll
    for (int a = 0; a < 4; a++) A[a] = make_float2(0.f,0.f);
    for (int n2 = 0; n2 < cp; n2++){
        float2 w = W[n2*cp + k2];
        #pragma unroll
        for (int a = 0; a < 4; a++){
            float v = srow[ty][a][n2];
            A[a].x = fmaf(v,  w.x, A[a].x);
            A[a].y = fmaf(-v, w.y, A[a].y);
        }
    }
    float2* G = d_G + (size_t)img*64*33;
    #pragma unroll
    for (int a = 0; a < 4; a++){
        int n1 = n1b + a;
        if (n1 < cp) G[(size_t)n1*33 + k2] = A[a];
    }
}

// ---------------- K8b: shell entries of xf = rfft2(w)/cp^2, scatter into x_out ----------------
__global__ void k8b_kernel(int cp){
    __shared__ float2 tw[64];
    int img = blockIdx.x;
    {
        const float2* W = d_W + offW(cp);
        for (int t = threadIdx.x; t < cp; t += blockDim.x) tw[t] = W[cp + t];
    }
    __syncthreads();
    int h = cp/2;
    int codd = cp & 1;
    int nE = (codd ? 2*(h+1) : (h+1)) + cp;
    int e = threadIdx.x;
    if (e >= nE) return;
    int rho, k2, trow;
    if (codd){
        if (e < h+1)            { rho = h;   k2 = e;        trow = h; }
        else if (e < 2*(h+1))   { rho = h+1; k2 = e-(h+1);  trow = 64-h; }
        else { int q = e - 2*(h+1); rho = q; k2 = h; trow = (q <= h) ? q : 64 - (cp - q); }
    } else {
        if (e < h+1)            { rho = h;   k2 = e;        trow = 64-h; }
        else { int q = e - (h+1);   rho = q; k2 = h; trow = (q < h) ? q : 64 - (cp - q); }
    }
    const float2* G = d_G + (size_t)img*64*33;
    float2 A = make_float2(0.f,0.f); int t = 0;
    for (int n1 = 0; n1 < cp; n1++){
        float2 v = G[(size_t)n1*33 + k2];
        float2 w = tw[t];
        A.x = fmaf(v.x, w.x, fmaf( v.y, w.y, A.x));
        A.y = fmaf(v.y, w.x, fmaf(-v.x, w.y, A.y));
        t += rho; if (t >= cp) t -= cp;
    }
    float inv = 1.f/((float)cp*(float)cp);
    d_xo[(size_t)img*64*33 + (size_t)trow*33 + k2] = make_float2(A.x*inv, A.y*inv);
}

// ---------------- K8base: full 8x5 spectrum block for base resolution ----------------
__global__ void k8base_kernel(){
    int img = blockIdx.x;
    int e = threadIdx.x;
    if (e >= 40) return;
    int q = e/5, k2 = e%5;
    const float2* W8 = d_W;
    const float2* G = d_G + (size_t)img*64*33;
    float2 A = make_float2(0.f,0.f);
    for (int n1 = 0; n1 < 8; n1++){
        float2 v = G[(size_t)n1*33 + k2];
        float2 w = W8[q*8 + n1];
        A.x = fmaf(v.x, w.x, fmaf( v.y, w.y, A.x));
        A.y = fmaf(v.y, w.x, fmaf(-v.x, w.y, A.y));
    }
    int trow = (q < 4) ? q : (56 + q);
    d_xo[(size_t)img*64*33 + (size_t)trow*33 + k2] = make_float2(A.x*(1.f/64.f), A.y*(1.f/64.f));
}

// ---------------- K9: analytic fft2(irfft2(x_out)) symmetrization -> output ----------------
__global__ void k9_kernel(float* __restrict__ out){
    int img = blockIdx.y;
    int k1  = blockIdx.x;
    int k2  = threadIdx.x;
    const float2* xo = d_xo + (size_t)img*64*33;
    int k1n = (64 - k1) & 63;
    float2 v;
    if (k2 >= 1 && k2 <= 31){
        v = xo[(size_t)k1*33 + k2];
    } else if (k2 >= 33){
        float2 a = xo[(size_t)k1n*33 + (64 - k2)];
        v = make_float2(a.x, -a.y);
    } else {
        float2 a = xo[(size_t)k1*33 + k2];
        float2 b = xo[(size_t)k1n*33 + k2];
        v = make_float2(0.5f*(a.x + b.x), 0.5f*(a.y - b.y));
    }
    size_t o = (((size_t)img*64 + k1)*64 + k2)*2;
    out[o]   = v.x;
    out[o+1] = v.y;
}

static inline int rup32(int n){ return ((n + 31)/32)*32; }
static inline int imbFor(int tx){
    int i = 256 / tx;
    if (i > 8) i = 8;
    if (i < 1) i = 1;
    while (i & (i-1)) i--;
    return i;
}

extern "C" void kernel_launch(void* const* d_in, const int* in_sizes, int n_in,
                              void* d_out, int out_size){
    const float* x = (const float*)d_in[0];
    float* out = (float*)d_out;
    (void)in_sizes; (void)n_in; (void)out_size;

    kW_kernel<<<121, 256>>>();

    k0a_kernel<<<dim3(32, BC/2), dim3(96, 2)>>>(x);
    k0b_kernel<<<dim3(32, BC/2), dim3(96, 2)>>>();
    kzero_kernel<<<2048, 256>>>();

    for (int r = 16; r <= 128; r += 2){
        int c    = r/2 + 1;
        int m    = r/2;
        int rp   = (m + 1)/2;
        int c2   = m/2 + 1;
        int cp   = r/2;
        int ncol = cp/2 + 1;
        int nq   = m/2 + 1;
        float invr2 = 1.f/((float)r*(float)r);

        int TX1 = rup32(c),    I1 = imbFor(TX1);
        int TX2 = rup32(r),    I2 = imbFor(TX2);
        int TXm = rup32(m),    Im = imbFor(TXm);
        int TX4 = rup32(c2),   I4 = imbFor(TX4);
        int TX8 = rup32(ncol), I8 = imbFor(TX8);

        if ((r % 4) == 0 && r >= 32)
            k1r4_kernel<<<dim3(r/4,     BC/I1), dim3(TX1, I1)>>>(r);
        else
            k1_kernel  <<<dim3((m+1)/2, BC/I1), dim3(TX1, I1)>>>(r);
        k2_kernel <<<dim3(r/2,      BC/Im), dim3(TXm, Im)>>>(r);
        k3_kernel <<<dim3((nq+1)/2, BC/I2), dim3(TX2, I2)>>>(r, m, rp);
        k4_kernel <<<dim3((m+1)/2,  BC/I4), dim3(TX4, I4)>>>(r, c2, invr2, m);
        k5_kernel <<<dim3((r+3)/4,  BC/I4), dim3(TX4, I4)>>>(r, m, rp, c2);
        k6_kernel <<<dim3(r/2,      BC/Im), dim3(TXm, Im)>>>(r, c2);
        k8a_kernel<<<dim3((cp+3)/4, BC/I8), dim3(TX8, I8)>>>(cp, ncol);
        if (r == 16) k8base_kernel<<<BC, 64>>>();
        else         k8b_kernel<<<BC, 128>>>(cp);
    }

    k9_kernel<<<dim3(64, BC), 64>>>(out);
}